// round 1
// baseline (speedup 1.0000x reference)
#include <cuda_runtime.h>
#include <math.h>

#define D_MODEL 2048
#define NH      16
#define DK      128
#define SEQ     2048
#define BATCH   2
#define KDIM    2048
#define MDIM    (BATCH*SEQ)   // 4096

// -------- scratch (static device allocations; no cudaMalloc allowed) --------
__device__ float g_Q[BATCH*NH*SEQ*DK];     // [b,h,s,d]
__device__ float g_K[BATCH*NH*SEQ*DK];
__device__ float g_V[BATCH*NH*SEQ*DK];
__device__ float g_att[BATCH*SEQ*D_MODEL]; // [b,s,h*128+d]

// ============================================================================
// NT SGEMM: C = A * B^T.  A[M,K] row-major, B[N,K] row-major. M=4096,N=2048,K=2048.
// mode 0: -> g_Q with RoPE   mode 1: -> g_K with RoPE
// mode 2: -> g_V (no rope)   mode 3: A = g_att, -> Cplain (d_out)
// Tile: BM=BN=128, BK=16, 256 threads, 8x8 per thread.
// ============================================================================
__global__ __launch_bounds__(256) void sgemm_nt(const float* __restrict__ A,
                                                const float* __restrict__ Bw,
                                                float* __restrict__ Cplain,
                                                const int* __restrict__ pos,
                                                int mode)
{
    __shared__ float As[16][128];
    __shared__ float Bs[16][128];

    const int tid  = threadIdx.x;
    const int trow = tid >> 4;          // 0..15
    const int tcol = tid & 15;          // 0..15
    const int m0   = blockIdx.y * 128;
    const int n0   = blockIdx.x * 128;

    const float* __restrict__ Ap = (mode == 3) ? g_att : A;

    const int la_r = tid >> 2;          // 0..63
    const int la_c = (tid & 3) << 2;    // 0,4,8,12

    float acc[8][8];
    #pragma unroll
    for (int i = 0; i < 8; i++)
        #pragma unroll
        for (int j = 0; j < 8; j++) acc[i][j] = 0.0f;

    for (int kt = 0; kt < KDIM; kt += 16) {
        #pragma unroll
        for (int rr = 0; rr < 2; rr++) {
            int r = la_r + rr * 64;
            float4 v = *(const float4*)&Ap[(size_t)(m0 + r) * KDIM + kt + la_c];
            As[la_c + 0][r] = v.x;
            As[la_c + 1][r] = v.y;
            As[la_c + 2][r] = v.z;
            As[la_c + 3][r] = v.w;
            float4 w = *(const float4*)&Bw[(size_t)(n0 + r) * KDIM + kt + la_c];
            Bs[la_c + 0][r] = w.x;
            Bs[la_c + 1][r] = w.y;
            Bs[la_c + 2][r] = w.z;
            Bs[la_c + 3][r] = w.w;
        }
        __syncthreads();

        #pragma unroll
        for (int kk = 0; kk < 16; kk++) {
            float a[8], b[8];
            *(float4*)&a[0] = *(const float4*)&As[kk][trow * 8];
            *(float4*)&a[4] = *(const float4*)&As[kk][trow * 8 + 4];
            *(float4*)&b[0] = *(const float4*)&Bs[kk][tcol * 8];
            *(float4*)&b[4] = *(const float4*)&Bs[kk][tcol * 8 + 4];
            #pragma unroll
            for (int i = 0; i < 8; i++)
                #pragma unroll
                for (int j = 0; j < 8; j++)
                    acc[i][j] = fmaf(a[i], b[j], acc[i][j]);
        }
        __syncthreads();
    }

    if (mode == 3) {
        #pragma unroll
        for (int i = 0; i < 8; i++) {
            int row = m0 + trow * 8 + i;
            float* o = &Cplain[(size_t)row * D_MODEL + n0 + tcol * 8];
            *(float4*)&o[0] = make_float4(acc[i][0], acc[i][1], acc[i][2], acc[i][3]);
            *(float4*)&o[4] = make_float4(acc[i][4], acc[i][5], acc[i][6], acc[i][7]);
        }
        return;
    }

    float* __restrict__ dst = (mode == 0) ? g_Q : ((mode == 1) ? g_K : g_V);
    const int h = blockIdx.x;           // N-tile == one head (128 cols)

    #pragma unroll
    for (int i = 0; i < 8; i++) {
        int m = m0 + trow * 8 + i;
        int b = m >> 11;                // / SEQ
        int s = m & 2047;
        if (mode != 2) {
            // RoPE: pairs (d, d+1), freq = theta^(-d/128) for even d
            float p = (float)pos[s];
            #pragma unroll
            for (int j = 0; j < 8; j += 2) {
                int d = tcol * 8 + j;   // even
                float freq = (float)exp(-(double)d * (9.210340371976184 / 128.0));
                float angf = p * freq;  // fp32 angle (matches reference)
                // accurate range reduction (immune to fast-math sincos)
                double a  = (double)angf;
                double q  = rint(a * 0.15915494309189535);
                float red = (float)(a - q * 6.283185307179586);
                float sn, cs;
                sincosf(red, &sn, &cs);
                float e = acc[i][j], o = acc[i][j + 1];
                acc[i][j]     = e * cs - o * sn;
                acc[i][j + 1] = e * sn + o * cs;
            }
        }
        float* o = &dst[(size_t)(((b * NH + h) * SEQ) + s) * DK + tcol * 8];
        *(float4*)&o[0] = make_float4(acc[i][0], acc[i][1], acc[i][2], acc[i][3]);
        *(float4*)&o[4] = make_float4(acc[i][4], acc[i][5], acc[i][6], acc[i][7]);
    }
}

// ============================================================================
// Causal flash attention. Block = (q-tile of 64, bh). 256 threads (16x16).
// Each thread: 4x4 score fragment, 4x8 output fragment.
// smem: Qs/Ks/Vs 64x129 (pad), Ps 64x65.
// ============================================================================
#define FLASH_SMEM ((3 * 64 * 129 + 64 * 65) * 4)

__global__ __launch_bounds__(256, 1) void flash_attn()
{
    extern __shared__ float sm[];
    float* Qs = sm;                 // 64 x 129
    float* Ks = sm + 64 * 129;
    float* Vs = sm + 2 * 64 * 129;
    float* Ps = sm + 3 * 64 * 129;  // 64 x 65

    const int tid = threadIdx.x;
    const int ty  = tid >> 4;       // 0..15
    const int tx  = tid & 15;       // 0..15
    const int qt  = blockIdx.x;
    const int bh  = blockIdx.y;
    const int q0  = qt * 64;
    const int r0  = ty * 4;         // score rows
    const int c0  = tx * 4;         // score cols
    const int oc0 = tx * 8;         // output cols
    const float scale = 0.08838834764831845f;  // 1/sqrt(128)

    // Load Q tile (pre-scaled)
    for (int idx = tid; idx < 64 * 32; idx += 256) {
        int r  = idx >> 5;
        int d0 = (idx & 31) << 2;
        float4 v = *(const float4*)&g_Q[(size_t)(bh * SEQ + q0 + r) * DK + d0];
        Qs[r * 129 + d0 + 0] = v.x * scale;
        Qs[r * 129 + d0 + 1] = v.y * scale;
        Qs[r * 129 + d0 + 2] = v.z * scale;
        Qs[r * 129 + d0 + 3] = v.w * scale;
    }

    float accO[4][8];
    #pragma unroll
    for (int i = 0; i < 4; i++)
        #pragma unroll
        for (int j = 0; j < 8; j++) accO[i][j] = 0.0f;
    float mrow[4] = {-INFINITY, -INFINITY, -INFINITY, -INFINITY};
    float lrow[4] = {0.0f, 0.0f, 0.0f, 0.0f};

    for (int kt = 0; kt <= qt; kt++) {
        const int k0 = kt * 64;
        __syncthreads();   // protect Ks/Vs/Ps from previous iteration readers
        for (int idx = tid; idx < 64 * 32; idx += 256) {
            int r  = idx >> 5;
            int d0 = (idx & 31) << 2;
            float4 kv = *(const float4*)&g_K[(size_t)(bh * SEQ + k0 + r) * DK + d0];
            Ks[r * 129 + d0 + 0] = kv.x;
            Ks[r * 129 + d0 + 1] = kv.y;
            Ks[r * 129 + d0 + 2] = kv.z;
            Ks[r * 129 + d0 + 3] = kv.w;
            float4 vv = *(const float4*)&g_V[(size_t)(bh * SEQ + k0 + r) * DK + d0];
            Vs[r * 129 + d0 + 0] = vv.x;
            Vs[r * 129 + d0 + 1] = vv.y;
            Vs[r * 129 + d0 + 2] = vv.z;
            Vs[r * 129 + d0 + 3] = vv.w;
        }
        __syncthreads();

        // ---- scores: 4x4 fragment over d=0..127 ----
        float s[4][4];
        #pragma unroll
        for (int i = 0; i < 4; i++)
            #pragma unroll
            for (int j = 0; j < 4; j++) s[i][j] = 0.0f;

        #pragma unroll 4
        for (int d = 0; d < 128; d++) {
            float qv[4], kv[4];
            #pragma unroll
            for (int i = 0; i < 4; i++) qv[i] = Qs[(r0 + i) * 129 + d];
            #pragma unroll
            for (int j = 0; j < 4; j++) kv[j] = Ks[(c0 + j) * 129 + d];
            #pragma unroll
            for (int i = 0; i < 4; i++)
                #pragma unroll
                for (int j = 0; j < 4; j++)
                    s[i][j] = fmaf(qv[i], kv[j], s[i][j]);
        }

        // causal mask (only active on diagonal tile)
        #pragma unroll
        for (int i = 0; i < 4; i++)
            #pragma unroll
            for (int j = 0; j < 4; j++)
                if (k0 + c0 + j > q0 + r0 + i) s[i][j] = -INFINITY;

        // ---- online softmax update (rows shared across the 16 tx lanes) ----
        #pragma unroll
        for (int i = 0; i < 4; i++) {
            float mt = fmaxf(fmaxf(s[i][0], s[i][1]), fmaxf(s[i][2], s[i][3]));
            #pragma unroll
            for (int off = 1; off < 16; off <<= 1)
                mt = fmaxf(mt, __shfl_xor_sync(0xffffffffu, mt, off));
            float mnew  = fmaxf(mrow[i], mt);
            float alpha = expf(mrow[i] - mnew);   // 0 on first tile
            float psum  = 0.0f;
            #pragma unroll
            for (int j = 0; j < 4; j++) {
                float p = expf(s[i][j] - mnew);
                Ps[(r0 + i) * 65 + c0 + j] = p;
                psum += p;
            }
            #pragma unroll
            for (int off = 1; off < 16; off <<= 1)
                psum += __shfl_xor_sync(0xffffffffu, psum, off);
            lrow[i] = lrow[i] * alpha + psum;
            mrow[i] = mnew;
            #pragma unroll
            for (int j = 0; j < 8; j++) accO[i][j] *= alpha;
        }
        __syncthreads();   // Ps visible to all

        // ---- PV: accO[4][8] += P[4][64] * V[64][8] ----
        #pragma unroll 2
        for (int k = 0; k < 64; k++) {
            float pv[4], vv[8];
            #pragma unroll
            for (int i = 0; i < 4; i++) pv[i] = Ps[(r0 + i) * 65 + k];
            #pragma unroll
            for (int j = 0; j < 8; j++) vv[j] = Vs[k * 129 + oc0 + j];
            #pragma unroll
            for (int i = 0; i < 4; i++)
                #pragma unroll
                for (int j = 0; j < 8; j++)
                    accO[i][j] = fmaf(pv[i], vv[j], accO[i][j]);
        }
    }

    // ---- finalize and store in [B,S,D_MODEL] layout ----
    const int b = bh >> 4;
    const int h = bh & 15;
    #pragma unroll
    for (int i = 0; i < 4; i++) {
        float inv = 1.0f / lrow[i];
        int row = q0 + r0 + i;
        float* o = &g_att[(size_t)(b * SEQ + row) * D_MODEL + h * DK + oc0];
        *(float4*)&o[0] = make_float4(accO[i][0]*inv, accO[i][1]*inv,
                                      accO[i][2]*inv, accO[i][3]*inv);
        *(float4*)&o[4] = make_float4(accO[i][4]*inv, accO[i][5]*inv,
                                      accO[i][6]*inv, accO[i][7]*inv);
    }
}

// ============================================================================
extern "C" void kernel_launch(void* const* d_in, const int* in_sizes, int n_in,
                              void* d_out, int out_size)
{
    const float* x   = (const float*)d_in[0];
    const float* wq  = (const float*)d_in[1];
    const float* wk  = (const float*)d_in[2];
    const float* wv  = (const float*)d_in[3];
    const float* wo  = (const float*)d_in[4];
    const int*   pos = (const int*)  d_in[5];
    float* out = (float*)d_out;

    cudaFuncSetAttribute(flash_attn, cudaFuncAttributeMaxDynamicSharedMemorySize,
                         FLASH_SMEM);

    dim3 gg(D_MODEL / 128, MDIM / 128);   // 16 x 32
    sgemm_nt<<<gg, 256>>>(x, wq, nullptr, pos, 0);   // Q + RoPE
    sgemm_nt<<<gg, 256>>>(x, wk, nullptr, pos, 1);   // K + RoPE
    sgemm_nt<<<gg, 256>>>(x, wv, nullptr, pos, 2);   // V
    flash_attn<<<dim3(SEQ / 64, BATCH * NH), 256, FLASH_SMEM>>>();
    sgemm_nt<<<gg, 256>>>(nullptr, wo, out, pos, 3); // output projection
}

// round 3
// speedup vs baseline: 1.7995x; 1.7995x over previous
#include <cuda_runtime.h>
#include <math.h>
#include <stdint.h>

#define D_MODEL 2048
#define NH      16
#define DK      128
#define SEQ     2048
#define BATCH   2
#define KDIM    2048
#define MDIM    (BATCH*SEQ)   // 4096

// -------- scratch (static device memory; no cudaMalloc allowed) ------------
__device__ float g_Q[BATCH*NH*SEQ*DK];       // [b,h,s,d]
__device__ float g_K[BATCH*NH*SEQ*DK];
__device__ float g_V[BATCH*NH*SEQ*DK];
__device__ float g_att[BATCH*SEQ*D_MODEL];   // [b,s,h*128+d] (tf32-rounded)
__device__ float g_xr [MDIM*KDIM];           // tf32-rounded x
__device__ float g_wqr[KDIM*KDIM];
__device__ float g_wkr[KDIM*KDIM];
__device__ float g_wvr[KDIM*KDIM];
__device__ float g_wor[KDIM*KDIM];

// ============================================================================
// helpers
// ============================================================================
__device__ __forceinline__ float rtf32(float x) {
    uint32_t r;
    asm("cvt.rna.tf32.f32 %0, %1;" : "=r"(r) : "f"(x));
    return __uint_as_float(r);
}

__device__ __forceinline__ uint32_t smem_u32(const void* p) {
    uint32_t a;
    asm("{ .reg .u64 t; cvta.to.shared.u64 t, %1; cvt.u32.u64 %0, t; }"
        : "=r"(a) : "l"(p));
    return a;
}

#define CP16(dst, src) \
    asm volatile("cp.async.cg.shared.global [%0], [%1], 16;" \
                 :: "r"(dst), "l"(src) : "memory")
#define CP_COMMIT()  asm volatile("cp.async.commit_group;" ::: "memory")
#define CP_WAIT(n)   asm volatile("cp.async.wait_group %0;" :: "n"(n) : "memory")

__device__ __forceinline__ void mma_tf32(float& d0, float& d1, float& d2, float& d3,
                                         uint32_t a0, uint32_t a1, uint32_t a2, uint32_t a3,
                                         uint32_t b0, uint32_t b1) {
    asm volatile(
        "mma.sync.aligned.m16n8k8.row.col.f32.tf32.tf32.f32 "
        "{%0,%1,%2,%3}, {%4,%5,%6,%7}, {%8,%9}, {%0,%1,%2,%3};"
        : "+f"(d0), "+f"(d1), "+f"(d2), "+f"(d3)
        : "r"(a0), "r"(a1), "r"(a2), "r"(a3), "r"(b0), "r"(b1));
}

// ============================================================================
// prep: round fp32 -> tf32 (RNA).  mode: 0=x, 1..4 = wq,wk,wv,wo
// ============================================================================
__global__ void round_tf32(const float* __restrict__ src, int mode)
{
    float* dst = (mode == 0) ? g_xr :
                 (mode == 1) ? g_wqr :
                 (mode == 2) ? g_wkr :
                 (mode == 3) ? g_wvr : g_wor;
    size_t i = ((size_t)blockIdx.x * blockDim.x + threadIdx.x) * 4;
    float4 v = *(const float4*)&src[i];
    v.x = rtf32(v.x); v.y = rtf32(v.y); v.z = rtf32(v.z); v.w = rtf32(v.w);
    *(float4*)&dst[i] = v;
}

// ============================================================================
// tf32 mma.sync NT GEMM: C = A * B^T, A[M,K], B[N,K] row-major.
// Tile 128x128, BK=32, 256 thr, warp tile 32x64 (2x8 m16n8k8 frags).
// Smem stride 36 floats -> conflict-free fragment LDS. cp.async double buffer.
// mode 0: -> g_Q + RoPE   mode 1: -> g_K + RoPE   mode 2: -> g_V
// mode 3: A = g_att -> Cout (d_out)
// ============================================================================
#define TSTRIDE 36                        // floats per smem row
#define TILEF   (128 * TSTRIDE)           // 4608 floats = 18432 B
#define STAGEF  (2 * TILEF)               // A + B per stage
#define GEMM_SMEM (2 * STAGEF * 4)        // 73728 B

__global__ __launch_bounds__(256, 2) void gemm_mma(float* __restrict__ Cout,
                                                   const int* __restrict__ pos,
                                                   int mode)
{
    extern __shared__ float smf[];
    const int tid = threadIdx.x;
    const int wid = tid >> 5;
    const int lane = tid & 31;
    const int g = lane >> 2;              // 0..7
    const int cl = lane & 3;              // 0..3
    const int wm = wid & 3;               // 0..3  (m direction, 32 rows each)
    const int wn = wid >> 2;              // 0..1  (n direction, 64 cols each)
    const int m0 = blockIdx.y * 128;
    const int n0 = blockIdx.x * 128;

    const float* __restrict__ Ap = (mode == 3) ? g_att : g_xr;
    const float* __restrict__ Bp = (mode == 0) ? g_wqr :
                                   (mode == 1) ? g_wkr :
                                   (mode == 2) ? g_wvr : g_wor;
    const float* __restrict__ arow = Ap + (size_t)m0 * KDIM;
    const float* __restrict__ brow = Bp + (size_t)n0 * KDIM;

    const uint32_t sb = smem_u32(smf);
    // per-thread cp.async coords: 1024 float4 per tile, 256 thr -> 4 each
    const int ldr  = tid >> 3;            // 0..31 base row
    const int ldc4 = (tid & 7) << 2;      // 0,4,..,28 col

    // issue one stage worth of cp.async (A then B)
    auto load_tile = [&](int stage, int kt) {
        uint32_t base = sb + stage * STAGEF * 4;
        #pragma unroll
        for (int i = 0; i < 4; i++) {
            int r = ldr + i * 32;
            uint32_t doff = base + (r * TSTRIDE + ldc4) * 4;
            CP16(doff,            &arow[(size_t)r * KDIM + kt + ldc4]);
            CP16(doff + TILEF*4,  &brow[(size_t)r * KDIM + kt + ldc4]);
        }
    };

    float acc[2][8][4];
    #pragma unroll
    for (int i = 0; i < 2; i++)
        #pragma unroll
        for (int j = 0; j < 8; j++)
            #pragma unroll
            for (int k = 0; k < 4; k++) acc[i][j][k] = 0.0f;

    load_tile(0, 0);
    CP_COMMIT();

    const int aoff0 = (wm * 32 + g) * TSTRIDE + cl;
    const int boff0 = (wn * 64 + g) * TSTRIDE + cl;

    for (int c = 0; c < 64; c++) {
        if (c + 1 < 64) {
            load_tile((c + 1) & 1, (c + 1) * 32);
            CP_COMMIT();
            CP_WAIT(1);
        } else {
            CP_WAIT(0);
        }
        __syncthreads();

        const float* As = smf + (c & 1) * STAGEF;
        const float* Bs = As + TILEF;

        #pragma unroll
        for (int ks = 0; ks < 4; ks++) {
            uint32_t a[2][4], b[8][2];
            #pragma unroll
            for (int mf = 0; mf < 2; mf++) {
                int o = aoff0 + mf * 16 * TSTRIDE + ks * 8;
                a[mf][0] = __float_as_uint(As[o]);
                a[mf][1] = __float_as_uint(As[o + 8 * TSTRIDE]);
                a[mf][2] = __float_as_uint(As[o + 4]);
                a[mf][3] = __float_as_uint(As[o + 8 * TSTRIDE + 4]);
            }
            #pragma unroll
            for (int nf = 0; nf < 8; nf++) {
                int o = boff0 + nf * 8 * TSTRIDE + ks * 8;
                b[nf][0] = __float_as_uint(Bs[o]);
                b[nf][1] = __float_as_uint(Bs[o + 4]);
            }
            #pragma unroll
            for (int mf = 0; mf < 2; mf++)
                #pragma unroll
                for (int nf = 0; nf < 8; nf++)
                    mma_tf32(acc[mf][nf][0], acc[mf][nf][1],
                             acc[mf][nf][2], acc[mf][nf][3],
                             a[mf][0], a[mf][1], a[mf][2], a[mf][3],
                             b[nf][0], b[nf][1]);
        }
        __syncthreads();
    }

    // ---- epilogue ----
    // accum frag: c0/c1 at (row g, cols 2cl, 2cl+1), c2/c3 at row g+8
    if (mode == 3) {
        #pragma unroll
        for (int mf = 0; mf < 2; mf++) {
            #pragma unroll
            for (int half = 0; half < 2; half++) {
                int m = m0 + wm * 32 + mf * 16 + g + half * 8;
                float* o = &Cout[(size_t)m * D_MODEL + n0 + wn * 64 + cl * 2];
                #pragma unroll
                for (int nf = 0; nf < 8; nf++)
                    *(float2*)&o[nf * 8] =
                        make_float2(acc[mf][nf][half * 2], acc[mf][nf][half * 2 + 1]);
            }
        }
        return;
    }

    float* dptr = (mode == 0) ? g_Q : ((mode == 1) ? g_K : g_V);
    const int h = blockIdx.x;

    #pragma unroll
    for (int mf = 0; mf < 2; mf++) {
        #pragma unroll
        for (int half = 0; half < 2; half++) {
            int m = m0 + wm * 32 + mf * 16 + g + half * 8;
            int b = m >> 11;
            int s = m & 2047;
            float p = (mode != 2) ? (float)pos[s] : 0.0f;
            float* o = &dptr[(size_t)((b * NH + h) * SEQ + s) * DK + wn * 64 + cl * 2];
            #pragma unroll
            for (int nf = 0; nf < 8; nf++) {
                float e = acc[mf][nf][half * 2];
                float od = acc[mf][nf][half * 2 + 1];
                if (mode != 2) {
                    int d = wn * 64 + nf * 8 + cl * 2;   // even
                    float freq = (float)exp(-(double)d * (9.210340371976184 / 128.0));
                    double ang = (double)(p * freq);
                    double q   = rint(ang * 0.15915494309189535);
                    float red  = (float)(ang - q * 6.283185307179586);
                    float sn, cs;
                    sincosf(red, &sn, &cs);
                    float e2 = e * cs - od * sn;
                    od = e * sn + od * cs;
                    e = e2;
                }
                *(float2*)&o[nf * 8] = make_float2(e, od);
            }
        }
    }
}

// ============================================================================
// Causal flash attention (FFMA fp32; unchanged except tf32-rounded store).
// ============================================================================
#define FLASH_SMEM ((3 * 64 * 129 + 64 * 65) * 4)

__global__ __launch_bounds__(256, 1) void flash_attn()
{
    extern __shared__ float smf[];
    float* Qs = smf;
    float* Ks = smf + 64 * 129;
    float* Vs = smf + 2 * 64 * 129;
    float* Ps = smf + 3 * 64 * 129;

    const int tid = threadIdx.x;
    const int ty  = tid >> 4;
    const int tx  = tid & 15;
    const int qt  = blockIdx.x;
    const int bh  = blockIdx.y;
    const int q0  = qt * 64;
    const int r0  = ty * 4;
    const int c0  = tx * 4;
    const int oc0 = tx * 8;
    const float scale = 0.08838834764831845f;

    for (int idx = tid; idx < 64 * 32; idx += 256) {
        int r  = idx >> 5;
        int d0 = (idx & 31) << 2;
        float4 v = *(const float4*)&g_Q[(size_t)(bh * SEQ + q0 + r) * DK + d0];
        Qs[r * 129 + d0 + 0] = v.x * scale;
        Qs[r * 129 + d0 + 1] = v.y * scale;
        Qs[r * 129 + d0 + 2] = v.z * scale;
        Qs[r * 129 + d0 + 3] = v.w * scale;
    }

    float accO[4][8];
    #pragma unroll
    for (int i = 0; i < 4; i++)
        #pragma unroll
        for (int j = 0; j < 8; j++) accO[i][j] = 0.0f;
    float mrow[4] = {-INFINITY, -INFINITY, -INFINITY, -INFINITY};
    float lrow[4] = {0.0f, 0.0f, 0.0f, 0.0f};

    for (int kt = 0; kt <= qt; kt++) {
        const int k0 = kt * 64;
        __syncthreads();
        for (int idx = tid; idx < 64 * 32; idx += 256) {
            int r  = idx >> 5;
            int d0 = (idx & 31) << 2;
            float4 kv = *(const float4*)&g_K[(size_t)(bh * SEQ + k0 + r) * DK + d0];
            Ks[r * 129 + d0 + 0] = kv.x;
            Ks[r * 129 + d0 + 1] = kv.y;
            Ks[r * 129 + d0 + 2] = kv.z;
            Ks[r * 129 + d0 + 3] = kv.w;
            float4 vv = *(const float4*)&g_V[(size_t)(bh * SEQ + k0 + r) * DK + d0];
            Vs[r * 129 + d0 + 0] = vv.x;
            Vs[r * 129 + d0 + 1] = vv.y;
            Vs[r * 129 + d0 + 2] = vv.z;
            Vs[r * 129 + d0 + 3] = vv.w;
        }
        __syncthreads();

        float s[4][4];
        #pragma unroll
        for (int i = 0; i < 4; i++)
            #pragma unroll
            for (int j = 0; j < 4; j++) s[i][j] = 0.0f;

        #pragma unroll 4
        for (int d = 0; d < 128; d++) {
            float qv[4], kv[4];
            #pragma unroll
            for (int i = 0; i < 4; i++) qv[i] = Qs[(r0 + i) * 129 + d];
            #pragma unroll
            for (int j = 0; j < 4; j++) kv[j] = Ks[(c0 + j) * 129 + d];
            #pragma unroll
            for (int i = 0; i < 4; i++)
                #pragma unroll
                for (int j = 0; j < 4; j++)
                    s[i][j] = fmaf(qv[i], kv[j], s[i][j]);
        }

        #pragma unroll
        for (int i = 0; i < 4; i++)
            #pragma unroll
            for (int j = 0; j < 4; j++)
                if (k0 + c0 + j > q0 + r0 + i) s[i][j] = -INFINITY;

        #pragma unroll
        for (int i = 0; i < 4; i++) {
            float mt = fmaxf(fmaxf(s[i][0], s[i][1]), fmaxf(s[i][2], s[i][3]));
            #pragma unroll
            for (int off = 1; off < 16; off <<= 1)
                mt = fmaxf(mt, __shfl_xor_sync(0xffffffffu, mt, off));
            float mnew  = fmaxf(mrow[i], mt);
            float alpha = expf(mrow[i] - mnew);
            float psum  = 0.0f;
            #pragma unroll
            for (int j = 0; j < 4; j++) {
                float p = expf(s[i][j] - mnew);
                Ps[(r0 + i) * 65 + c0 + j] = p;
                psum += p;
            }
            #pragma unroll
            for (int off = 1; off < 16; off <<= 1)
                psum += __shfl_xor_sync(0xffffffffu, psum, off);
            lrow[i] = lrow[i] * alpha + psum;
            mrow[i] = mnew;
            #pragma unroll
            for (int j = 0; j < 8; j++) accO[i][j] *= alpha;
        }
        __syncthreads();

        #pragma unroll 2
        for (int k = 0; k < 64; k++) {
            float pv[4], vv[8];
            #pragma unroll
            for (int i = 0; i < 4; i++) pv[i] = Ps[(r0 + i) * 65 + k];
            #pragma unroll
            for (int j = 0; j < 8; j++) vv[j] = Vs[k * 129 + oc0 + j];
            #pragma unroll
            for (int i = 0; i < 4; i++)
                #pragma unroll
                for (int j = 0; j < 8; j++)
                    accO[i][j] = fmaf(pv[i], vv[j], accO[i][j]);
        }
    }

    const int b = bh >> 4;
    const int h = bh & 15;
    #pragma unroll
    for (int i = 0; i < 4; i++) {
        float inv = 1.0f / lrow[i];
        int row = q0 + r0 + i;
        float* o = &g_att[(size_t)(b * SEQ + row) * D_MODEL + h * DK + oc0];
        // tf32-round here: this buffer feeds the tf32 wo GEMM
        *(float4*)&o[0] = make_float4(rtf32(accO[i][0]*inv), rtf32(accO[i][1]*inv),
                                      rtf32(accO[i][2]*inv), rtf32(accO[i][3]*inv));
        *(float4*)&o[4] = make_float4(rtf32(accO[i][4]*inv), rtf32(accO[i][5]*inv),
                                      rtf32(accO[i][6]*inv), rtf32(accO[i][7]*inv));
    }
}

// ============================================================================
extern "C" void kernel_launch(void* const* d_in, const int* in_sizes, int n_in,
                              void* d_out, int out_size)
{
    const float* x   = (const float*)d_in[0];
    const float* wq  = (const float*)d_in[1];
    const float* wk  = (const float*)d_in[2];
    const float* wv  = (const float*)d_in[3];
    const float* wo  = (const float*)d_in[4];
    const int*   pos = (const int*)  d_in[5];
    float* out = (float*)d_out;

    cudaFuncSetAttribute(gemm_mma, cudaFuncAttributeMaxDynamicSharedMemorySize,
                         GEMM_SMEM);
    cudaFuncSetAttribute(flash_attn, cudaFuncAttributeMaxDynamicSharedMemorySize,
                         FLASH_SMEM);

    // round inputs to tf32 (RNA) once
    round_tf32<<<(MDIM*KDIM)/1024, 256>>>(x,  0);
    round_tf32<<<(KDIM*KDIM)/1024, 256>>>(wq, 1);
    round_tf32<<<(KDIM*KDIM)/1024, 256>>>(wk, 2);
    round_tf32<<<(KDIM*KDIM)/1024, 256>>>(wv, 3);
    round_tf32<<<(KDIM*KDIM)/1024, 256>>>(wo, 4);

    dim3 gg(D_MODEL / 128, MDIM / 128);   // 16 x 32
    gemm_mma<<<gg, 256, GEMM_SMEM>>>(nullptr, pos, 0);   // Q + RoPE
    gemm_mma<<<gg, 256, GEMM_SMEM>>>(nullptr, pos, 1);   // K + RoPE
    gemm_mma<<<gg, 256, GEMM_SMEM>>>(nullptr, pos, 2);   // V
    flash_attn<<<dim3(SEQ / 64, BATCH * NH), 256, FLASH_SMEM>>>();
    gemm_mma<<<gg, 256, GEMM_SMEM>>>(out, pos, 3);       // output projection
}

// round 4
// speedup vs baseline: 1.8233x; 1.0132x over previous
#include <cuda_runtime.h>
#include <math.h>
#include <stdint.h>

#define D_MODEL 2048
#define NH      16
#define DK      128
#define SEQ     2048
#define BATCH   2
#define KDIM    2048
#define MDIM    (BATCH*SEQ)   // 4096

// -------- scratch (static device memory; no cudaMalloc allowed) ------------
__device__ float g_Q[BATCH*NH*SEQ*DK];       // [b,h,s,d]
__device__ float g_K[BATCH*NH*SEQ*DK];
__device__ float g_V[BATCH*NH*SEQ*DK];
__device__ float g_att[BATCH*SEQ*D_MODEL];   // [b,s,h*128+d] (tf32-rounded)
__device__ float g_xr [MDIM*KDIM];           // tf32-rounded x
__device__ float g_wqr[KDIM*KDIM];
__device__ float g_wkr[KDIM*KDIM];
__device__ float g_wvr[KDIM*KDIM];
__device__ float g_wor[KDIM*KDIM];

// ============================================================================
// helpers
// ============================================================================
__device__ __forceinline__ float rtf32(float x) {
    uint32_t r;
    asm("cvt.rna.tf32.f32 %0, %1;" : "=r"(r) : "f"(x));
    return __uint_as_float(r);
}

__device__ __forceinline__ uint32_t smem_u32(const void* p) {
    uint32_t a;
    asm("{ .reg .u64 t; cvta.to.shared.u64 t, %1; cvt.u32.u64 %0, t; }"
        : "=r"(a) : "l"(p));
    return a;
}

#define CP16(dst, src) \
    asm volatile("cp.async.cg.shared.global [%0], [%1], 16;" \
                 :: "r"(dst), "l"(src) : "memory")
#define CP_COMMIT()  asm volatile("cp.async.commit_group;" ::: "memory")
#define CP_WAIT(n)   asm volatile("cp.async.wait_group %0;" :: "n"(n) : "memory")

__device__ __forceinline__ void mma_tf32(float& d0, float& d1, float& d2, float& d3,
                                         uint32_t a0, uint32_t a1, uint32_t a2, uint32_t a3,
                                         uint32_t b0, uint32_t b1) {
    asm volatile(
        "mma.sync.aligned.m16n8k8.row.col.f32.tf32.tf32.f32 "
        "{%0,%1,%2,%3}, {%4,%5,%6,%7}, {%8,%9}, {%0,%1,%2,%3};"
        : "+f"(d0), "+f"(d1), "+f"(d2), "+f"(d3)
        : "r"(a0), "r"(a1), "r"(a2), "r"(a3), "r"(b0), "r"(b1));
}

// ============================================================================
// prep: round fp32 -> tf32 (RNA).  mode: 0=x, 1..4 = wq,wk,wv,wo
// ============================================================================
__global__ void round_tf32(const float* __restrict__ src, int mode)
{
    float* dst = (mode == 0) ? g_xr :
                 (mode == 1) ? g_wqr :
                 (mode == 2) ? g_wkr :
                 (mode == 3) ? g_wvr : g_wor;
    size_t i = ((size_t)blockIdx.x * blockDim.x + threadIdx.x) * 4;
    float4 v = *(const float4*)&src[i];
    v.x = rtf32(v.x); v.y = rtf32(v.y); v.z = rtf32(v.z); v.w = rtf32(v.w);
    *(float4*)&dst[i] = v;
}

// ============================================================================
// tf32 mma.sync NT GEMM: C = A * B^T, A[M,K], B[N,K] row-major.
// Tile 128x128, BK=32, 256 thr, warp tile 32x64 (2x8 m16n8k8 frags).
// Smem stride 36 floats -> conflict-free fragment LDS. cp.async double buffer.
// mode 0: -> g_Q + RoPE   mode 1: -> g_K + RoPE   mode 2: -> g_V
// mode 3: A = g_att -> Cout (d_out)
// ============================================================================
#define TSTRIDE 36                        // floats per smem row
#define TILEF   (128 * TSTRIDE)           // 4608 floats = 18432 B
#define STAGEF  (2 * TILEF)               // A + B per stage
#define GEMM_SMEM (2 * STAGEF * 4)        // 73728 B

__global__ __launch_bounds__(256, 2) void gemm_mma(float* __restrict__ Cout,
                                                   const int* __restrict__ pos,
                                                   int mode)
{
    extern __shared__ float smf[];
    const int tid = threadIdx.x;
    const int wid = tid >> 5;
    const int lane = tid & 31;
    const int g = lane >> 2;              // 0..7
    const int cl = lane & 3;              // 0..3
    const int wm = wid & 3;               // 0..3  (m direction, 32 rows each)
    const int wn = wid >> 2;              // 0..1  (n direction, 64 cols each)
    const int m0 = blockIdx.y * 128;
    const int n0 = blockIdx.x * 128;

    const float* __restrict__ Ap = (mode == 3) ? g_att : g_xr;
    const float* __restrict__ Bp = (mode == 0) ? g_wqr :
                                   (mode == 1) ? g_wkr :
                                   (mode == 2) ? g_wvr : g_wor;
    const float* __restrict__ arow = Ap + (size_t)m0 * KDIM;
    const float* __restrict__ brow = Bp + (size_t)n0 * KDIM;

    const uint32_t sb = smem_u32(smf);
    // per-thread cp.async coords: 1024 float4 per tile, 256 thr -> 4 each
    const int ldr  = tid >> 3;            // 0..31 base row
    const int ldc4 = (tid & 7) << 2;      // 0,4,..,28 col

    // issue one stage worth of cp.async (A then B)
    auto load_tile = [&](int stage, int kt) {
        uint32_t base = sb + stage * STAGEF * 4;
        #pragma unroll
        for (int i = 0; i < 4; i++) {
            int r = ldr + i * 32;
            uint32_t doff = base + (r * TSTRIDE + ldc4) * 4;
            CP16(doff,            &arow[(size_t)r * KDIM + kt + ldc4]);
            CP16(doff + TILEF*4,  &brow[(size_t)r * KDIM + kt + ldc4]);
        }
    };

    float acc[2][8][4];
    #pragma unroll
    for (int i = 0; i < 2; i++)
        #pragma unroll
        for (int j = 0; j < 8; j++)
            #pragma unroll
            for (int k = 0; k < 4; k++) acc[i][j][k] = 0.0f;

    load_tile(0, 0);
    CP_COMMIT();

    const int aoff0 = (wm * 32 + g) * TSTRIDE + cl;
    const int boff0 = (wn * 64 + g) * TSTRIDE + cl;

    for (int c = 0; c < 64; c++) {
        if (c + 1 < 64) {
            load_tile((c + 1) & 1, (c + 1) * 32);
            CP_COMMIT();
            CP_WAIT(1);
        } else {
            CP_WAIT(0);
        }
        __syncthreads();

        const float* As = smf + (c & 1) * STAGEF;
        const float* Bs = As + TILEF;

        #pragma unroll
        for (int ks = 0; ks < 4; ks++) {
            uint32_t a[2][4], b[8][2];
            #pragma unroll
            for (int mf = 0; mf < 2; mf++) {
                int o = aoff0 + mf * 16 * TSTRIDE + ks * 8;
                a[mf][0] = __float_as_uint(As[o]);
                a[mf][1] = __float_as_uint(As[o + 8 * TSTRIDE]);
                a[mf][2] = __float_as_uint(As[o + 4]);
                a[mf][3] = __float_as_uint(As[o + 8 * TSTRIDE + 4]);
            }
            #pragma unroll
            for (int nf = 0; nf < 8; nf++) {
                int o = boff0 + nf * 8 * TSTRIDE + ks * 8;
                b[nf][0] = __float_as_uint(Bs[o]);
                b[nf][1] = __float_as_uint(Bs[o + 4]);
            }
            #pragma unroll
            for (int mf = 0; mf < 2; mf++)
                #pragma unroll
                for (int nf = 0; nf < 8; nf++)
                    mma_tf32(acc[mf][nf][0], acc[mf][nf][1],
                             acc[mf][nf][2], acc[mf][nf][3],
                             a[mf][0], a[mf][1], a[mf][2], a[mf][3],
                             b[nf][0], b[nf][1]);
        }
        __syncthreads();
    }

    // ---- epilogue ----
    // accum frag: c0/c1 at (row g, cols 2cl, 2cl+1), c2/c3 at row g+8
    if (mode == 3) {
        #pragma unroll
        for (int mf = 0; mf < 2; mf++) {
            #pragma unroll
            for (int half = 0; half < 2; half++) {
                int m = m0 + wm * 32 + mf * 16 + g + half * 8;
                float* o = &Cout[(size_t)m * D_MODEL + n0 + wn * 64 + cl * 2];
                #pragma unroll
                for (int nf = 0; nf < 8; nf++)
                    *(float2*)&o[nf * 8] =
                        make_float2(acc[mf][nf][half * 2], acc[mf][nf][half * 2 + 1]);
            }
        }
        return;
    }

    float* dptr = (mode == 0) ? g_Q : ((mode == 1) ? g_K : g_V);
    const int h = blockIdx.x;

    #pragma unroll
    for (int mf = 0; mf < 2; mf++) {
        #pragma unroll
        for (int half = 0; half < 2; half++) {
            int m = m0 + wm * 32 + mf * 16 + g + half * 8;
            int b = m >> 11;
            int s = m & 2047;
            float p = (mode != 2) ? (float)pos[s] : 0.0f;
            float* o = &dptr[(size_t)((b * NH + h) * SEQ + s) * DK + wn * 64 + cl * 2];
            #pragma unroll
            for (int nf = 0; nf < 8; nf++) {
                float e = acc[mf][nf][half * 2];
                float od = acc[mf][nf][half * 2 + 1];
                if (mode != 2) {
                    int d = wn * 64 + nf * 8 + cl * 2;   // even
                    float freq = (float)exp(-(double)d * (9.210340371976184 / 128.0));
                    double ang = (double)(p * freq);
                    double q   = rint(ang * 0.15915494309189535);
                    float red  = (float)(ang - q * 6.283185307179586);
                    float sn, cs;
                    sincosf(red, &sn, &cs);
                    float e2 = e * cs - od * sn;
                    od = e * sn + od * cs;
                    e = e2;
                }
                *(float2*)&o[nf * 8] = make_float2(e, od);
            }
        }
    }
}

// ============================================================================
// Causal flash attention (FFMA fp32; unchanged except tf32-rounded store).
// ============================================================================
#define FLASH_SMEM ((3 * 64 * 129 + 64 * 65) * 4)

__global__ __launch_bounds__(256, 1) void flash_attn()
{
    extern __shared__ float smf[];
    float* Qs = smf;
    float* Ks = smf + 64 * 129;
    float* Vs = smf + 2 * 64 * 129;
    float* Ps = smf + 3 * 64 * 129;

    const int tid = threadIdx.x;
    const int ty  = tid >> 4;
    const int tx  = tid & 15;
    const int qt  = blockIdx.x;
    const int bh  = blockIdx.y;
    const int q0  = qt * 64;
    const int r0  = ty * 4;
    const int c0  = tx * 4;
    const int oc0 = tx * 8;
    const float scale = 0.08838834764831845f;

    for (int idx = tid; idx < 64 * 32; idx += 256) {
        int r  = idx >> 5;
        int d0 = (idx & 31) << 2;
        float4 v = *(const float4*)&g_Q[(size_t)(bh * SEQ + q0 + r) * DK + d0];
        Qs[r * 129 + d0 + 0] = v.x * scale;
        Qs[r * 129 + d0 + 1] = v.y * scale;
        Qs[r * 129 + d0 + 2] = v.z * scale;
        Qs[r * 129 + d0 + 3] = v.w * scale;
    }

    float accO[4][8];
    #pragma unroll
    for (int i = 0; i < 4; i++)
        #pragma unroll
        for (int j = 0; j < 8; j++) accO[i][j] = 0.0f;
    float mrow[4] = {-INFINITY, -INFINITY, -INFINITY, -INFINITY};
    float lrow[4] = {0.0f, 0.0f, 0.0f, 0.0f};

    for (int kt = 0; kt <= qt; kt++) {
        const int k0 = kt * 64;
        __syncthreads();
        for (int idx = tid; idx < 64 * 32; idx += 256) {
            int r  = idx >> 5;
            int d0 = (idx & 31) << 2;
            float4 kv = *(const float4*)&g_K[(size_t)(bh * SEQ + k0 + r) * DK + d0];
            Ks[r * 129 + d0 + 0] = kv.x;
            Ks[r * 129 + d0 + 1] = kv.y;
            Ks[r * 129 + d0 + 2] = kv.z;
            Ks[r * 129 + d0 + 3] = kv.w;
            float4 vv = *(const float4*)&g_V[(size_t)(bh * SEQ + k0 + r) * DK + d0];
            Vs[r * 129 + d0 + 0] = vv.x;
            Vs[r * 129 + d0 + 1] = vv.y;
            Vs[r * 129 + d0 + 2] = vv.z;
            Vs[r * 129 + d0 + 3] = vv.w;
        }
        __syncthreads();

        float s[4][4];
        #pragma unroll
        for (int i = 0; i < 4; i++)
            #pragma unroll
            for (int j = 0; j < 4; j++) s[i][j] = 0.0f;

        #pragma unroll 4
        for (int d = 0; d < 128; d++) {
            float qv[4], kv[4];
            #pragma unroll
            for (int i = 0; i < 4; i++) qv[i] = Qs[(r0 + i) * 129 + d];
            #pragma unroll
            for (int j = 0; j < 4; j++) kv[j] = Ks[(c0 + j) * 129 + d];
            #pragma unroll
            for (int i = 0; i < 4; i++)
                #pragma unroll
                for (int j = 0; j < 4; j++)
                    s[i][j] = fmaf(qv[i], kv[j], s[i][j]);
        }

        #pragma unroll
        for (int i = 0; i < 4; i++)
            #pragma unroll
            for (int j = 0; j < 4; j++)
                if (k0 + c0 + j > q0 + r0 + i) s[i][j] = -INFINITY;

        #pragma unroll
        for (int i = 0; i < 4; i++) {
            float mt = fmaxf(fmaxf(s[i][0], s[i][1]), fmaxf(s[i][2], s[i][3]));
            #pragma unroll
            for (int off = 1; off < 16; off <<= 1)
                mt = fmaxf(mt, __shfl_xor_sync(0xffffffffu, mt, off));
            float mnew  = fmaxf(mrow[i], mt);
            float alpha = expf(mrow[i] - mnew);
            float psum  = 0.0f;
            #pragma unroll
            for (int j = 0; j < 4; j++) {
                float p = expf(s[i][j] - mnew);
                Ps[(r0 + i) * 65 + c0 + j] = p;
                psum += p;
            }
            #pragma unroll
            for (int off = 1; off < 16; off <<= 1)
                psum += __shfl_xor_sync(0xffffffffu, psum, off);
            lrow[i] = lrow[i] * alpha + psum;
            mrow[i] = mnew;
            #pragma unroll
            for (int j = 0; j < 8; j++) accO[i][j] *= alpha;
        }
        __syncthreads();

        #pragma unroll 2
        for (int k = 0; k < 64; k++) {
            float pv[4], vv[8];
            #pragma unroll
            for (int i = 0; i < 4; i++) pv[i] = Ps[(r0 + i) * 65 + k];
            #pragma unroll
            for (int j = 0; j < 8; j++) vv[j] = Vs[k * 129 + oc0 + j];
            #pragma unroll
            for (int i = 0; i < 4; i++)
                #pragma unroll
                for (int j = 0; j < 8; j++)
                    accO[i][j] = fmaf(pv[i], vv[j], accO[i][j]);
        }
    }

    const int b = bh >> 4;
    const int h = bh & 15;
    #pragma unroll
    for (int i = 0; i < 4; i++) {
        float inv = 1.0f / lrow[i];
        int row = q0 + r0 + i;
        float* o = &g_att[(size_t)(b * SEQ + row) * D_MODEL + h * DK + oc0];
        // tf32-round here: this buffer feeds the tf32 wo GEMM
        *(float4*)&o[0] = make_float4(rtf32(accO[i][0]*inv), rtf32(accO[i][1]*inv),
                                      rtf32(accO[i][2]*inv), rtf32(accO[i][3]*inv));
        *(float4*)&o[4] = make_float4(rtf32(accO[i][4]*inv), rtf32(accO[i][5]*inv),
                                      rtf32(accO[i][6]*inv), rtf32(accO[i][7]*inv));
    }
}

// ============================================================================
extern "C" void kernel_launch(void* const* d_in, const int* in_sizes, int n_in,
                              void* d_out, int out_size)
{
    const float* x   = (const float*)d_in[0];
    const float* wq  = (const float*)d_in[1];
    const float* wk  = (const float*)d_in[2];
    const float* wv  = (const float*)d_in[3];
    const float* wo  = (const float*)d_in[4];
    const int*   pos = (const int*)  d_in[5];
    float* out = (float*)d_out;

    cudaFuncSetAttribute(gemm_mma, cudaFuncAttributeMaxDynamicSharedMemorySize,
                         GEMM_SMEM);
    cudaFuncSetAttribute(flash_attn, cudaFuncAttributeMaxDynamicSharedMemorySize,
                         FLASH_SMEM);

    // round inputs to tf32 (RNA) once
    round_tf32<<<(MDIM*KDIM)/1024, 256>>>(x,  0);
    round_tf32<<<(KDIM*KDIM)/1024, 256>>>(wq, 1);
    round_tf32<<<(KDIM*KDIM)/1024, 256>>>(wk, 2);
    round_tf32<<<(KDIM*KDIM)/1024, 256>>>(wv, 3);
    round_tf32<<<(KDIM*KDIM)/1024, 256>>>(wo, 4);

    dim3 gg(D_MODEL / 128, MDIM / 128);   // 16 x 32
    gemm_mma<<<gg, 256, GEMM_SMEM>>>(nullptr, pos, 0);   // Q + RoPE
    gemm_mma<<<gg, 256, GEMM_SMEM>>>(nullptr, pos, 1);   // K + RoPE
    gemm_mma<<<gg, 256, GEMM_SMEM>>>(nullptr, pos, 2);   // V
    flash_attn<<<dim3(SEQ / 64, BATCH * NH), 256, FLASH_SMEM>>>();
    gemm_mma<<<gg, 256, GEMM_SMEM>>>(out, pos, 3);       // output projection
}

// round 5
// speedup vs baseline: 4.0710x; 2.2328x over previous
#include <cuda_runtime.h>
#include <math.h>
#include <stdint.h>

#define D_MODEL 2048
#define NH      16
#define DK      128
#define SEQ     2048
#define BATCH   2
#define KDIM    2048
#define MDIM    (BATCH*SEQ)   // 4096

// -------- scratch (static device memory; no cudaMalloc allowed) ------------
__device__ float g_Q[BATCH*NH*SEQ*DK];       // [b,h,s,d]
__device__ float g_K[BATCH*NH*SEQ*DK];
__device__ float g_V[BATCH*NH*SEQ*DK];
__device__ float g_att[BATCH*SEQ*D_MODEL];   // [b,s,h*128+d] (tf32-rounded)
__device__ float g_xr [MDIM*KDIM];           // tf32-rounded x
__device__ float g_wqr[KDIM*KDIM];
__device__ float g_wkr[KDIM*KDIM];
__device__ float g_wvr[KDIM*KDIM];
__device__ float g_wor[KDIM*KDIM];

// ============================================================================
// helpers
// ============================================================================
__device__ __forceinline__ float rtf32(float x) {
    uint32_t r;
    asm("cvt.rna.tf32.f32 %0, %1;" : "=r"(r) : "f"(x));
    return __uint_as_float(r);
}

__device__ __forceinline__ uint32_t smem_u32(const void* p) {
    uint32_t a;
    asm("{ .reg .u64 t; cvta.to.shared.u64 t, %1; cvt.u32.u64 %0, t; }"
        : "=r"(a) : "l"(p));
    return a;
}

#define CP16(dst, src) \
    asm volatile("cp.async.cg.shared.global [%0], [%1], 16;" \
                 :: "r"(dst), "l"(src) : "memory")
#define CP_COMMIT()  asm volatile("cp.async.commit_group;" ::: "memory")
#define CP_WAIT(n)   asm volatile("cp.async.wait_group %0;" :: "n"(n) : "memory")

__device__ __forceinline__ void mma_tf32(float& d0, float& d1, float& d2, float& d3,
                                         uint32_t a0, uint32_t a1, uint32_t a2, uint32_t a3,
                                         uint32_t b0, uint32_t b1) {
    asm volatile(
        "mma.sync.aligned.m16n8k8.row.col.f32.tf32.tf32.f32 "
        "{%0,%1,%2,%3}, {%4,%5,%6,%7}, {%8,%9}, {%0,%1,%2,%3};"
        : "+f"(d0), "+f"(d1), "+f"(d2), "+f"(d3)
        : "r"(a0), "r"(a1), "r"(a2), "r"(a3), "r"(b0), "r"(b1));
}

// ============================================================================
// prep: round fp32 -> tf32 (RNA).  mode: 0=x, 1..4 = wq,wk,wv,wo
// ============================================================================
__global__ void round_tf32(const float* __restrict__ src, int mode)
{
    float* dst = (mode == 0) ? g_xr :
                 (mode == 1) ? g_wqr :
                 (mode == 2) ? g_wkr :
                 (mode == 3) ? g_wvr : g_wor;
    size_t i = ((size_t)blockIdx.x * blockDim.x + threadIdx.x) * 4;
    float4 v = *(const float4*)&src[i];
    v.x = rtf32(v.x); v.y = rtf32(v.y); v.z = rtf32(v.z); v.w = rtf32(v.w);
    *(float4*)&dst[i] = v;
}

// ============================================================================
// tf32 mma.sync NT GEMM (unchanged from R4 — known good).
// ============================================================================
#define TSTRIDE 36
#define TILEF   (128 * TSTRIDE)
#define STAGEF  (2 * TILEF)
#define GEMM_SMEM (2 * STAGEF * 4)

__global__ __launch_bounds__(256, 2) void gemm_mma(float* __restrict__ Cout,
                                                   const int* __restrict__ pos,
                                                   int mode)
{
    extern __shared__ float smf[];
    const int tid = threadIdx.x;
    const int wid = tid >> 5;
    const int lane = tid & 31;
    const int g = lane >> 2;
    const int cl = lane & 3;
    const int wm = wid & 3;
    const int wn = wid >> 2;
    const int m0 = blockIdx.y * 128;
    const int n0 = blockIdx.x * 128;

    const float* __restrict__ Ap = (mode == 3) ? g_att : g_xr;
    const float* __restrict__ Bp = (mode == 0) ? g_wqr :
                                   (mode == 1) ? g_wkr :
                                   (mode == 2) ? g_wvr : g_wor;
    const float* __restrict__ arow = Ap + (size_t)m0 * KDIM;
    const float* __restrict__ brow = Bp + (size_t)n0 * KDIM;

    const uint32_t sb = smem_u32(smf);
    const int ldr  = tid >> 3;
    const int ldc4 = (tid & 7) << 2;

    auto load_tile = [&](int stage, int kt) {
        uint32_t base = sb + stage * STAGEF * 4;
        #pragma unroll
        for (int i = 0; i < 4; i++) {
            int r = ldr + i * 32;
            uint32_t doff = base + (r * TSTRIDE + ldc4) * 4;
            CP16(doff,            &arow[(size_t)r * KDIM + kt + ldc4]);
            CP16(doff + TILEF*4,  &brow[(size_t)r * KDIM + kt + ldc4]);
        }
    };

    float acc[2][8][4];
    #pragma unroll
    for (int i = 0; i < 2; i++)
        #pragma unroll
        for (int j = 0; j < 8; j++)
            #pragma unroll
            for (int k = 0; k < 4; k++) acc[i][j][k] = 0.0f;

    load_tile(0, 0);
    CP_COMMIT();

    const int aoff0 = (wm * 32 + g) * TSTRIDE + cl;
    const int boff0 = (wn * 64 + g) * TSTRIDE + cl;

    for (int c = 0; c < 64; c++) {
        if (c + 1 < 64) {
            load_tile((c + 1) & 1, (c + 1) * 32);
            CP_COMMIT();
            CP_WAIT(1);
        } else {
            CP_WAIT(0);
        }
        __syncthreads();

        const float* As = smf + (c & 1) * STAGEF;
        const float* Bs = As + TILEF;

        #pragma unroll
        for (int ks = 0; ks < 4; ks++) {
            uint32_t a[2][4], b[8][2];
            #pragma unroll
            for (int mf = 0; mf < 2; mf++) {
                int o = aoff0 + mf * 16 * TSTRIDE + ks * 8;
                a[mf][0] = __float_as_uint(As[o]);
                a[mf][1] = __float_as_uint(As[o + 8 * TSTRIDE]);
                a[mf][2] = __float_as_uint(As[o + 4]);
                a[mf][3] = __float_as_uint(As[o + 8 * TSTRIDE + 4]);
            }
            #pragma unroll
            for (int nf = 0; nf < 8; nf++) {
                int o = boff0 + nf * 8 * TSTRIDE + ks * 8;
                b[nf][0] = __float_as_uint(Bs[o]);
                b[nf][1] = __float_as_uint(Bs[o + 4]);
            }
            #pragma unroll
            for (int mf = 0; mf < 2; mf++)
                #pragma unroll
                for (int nf = 0; nf < 8; nf++)
                    mma_tf32(acc[mf][nf][0], acc[mf][nf][1],
                             acc[mf][nf][2], acc[mf][nf][3],
                             a[mf][0], a[mf][1], a[mf][2], a[mf][3],
                             b[nf][0], b[nf][1]);
        }
        __syncthreads();
    }

    if (mode == 3) {
        #pragma unroll
        for (int mf = 0; mf < 2; mf++) {
            #pragma unroll
            for (int half = 0; half < 2; half++) {
                int m = m0 + wm * 32 + mf * 16 + g + half * 8;
                float* o = &Cout[(size_t)m * D_MODEL + n0 + wn * 64 + cl * 2];
                #pragma unroll
                for (int nf = 0; nf < 8; nf++)
                    *(float2*)&o[nf * 8] =
                        make_float2(acc[mf][nf][half * 2], acc[mf][nf][half * 2 + 1]);
            }
        }
        return;
    }

    float* dptr = (mode == 0) ? g_Q : ((mode == 1) ? g_K : g_V);
    const int h = blockIdx.x;

    #pragma unroll
    for (int mf = 0; mf < 2; mf++) {
        #pragma unroll
        for (int half = 0; half < 2; half++) {
            int m = m0 + wm * 32 + mf * 16 + g + half * 8;
            int b = m >> 11;
            int s = m & 2047;
            float p = (mode != 2) ? (float)pos[s] : 0.0f;
            float* o = &dptr[(size_t)((b * NH + h) * SEQ + s) * DK + wn * 64 + cl * 2];
            #pragma unroll
            for (int nf = 0; nf < 8; nf++) {
                float e = acc[mf][nf][half * 2];
                float od = acc[mf][nf][half * 2 + 1];
                if (mode != 2) {
                    int d = wn * 64 + nf * 8 + cl * 2;
                    float freq = (float)exp(-(double)d * (9.210340371976184 / 128.0));
                    double ang = (double)(p * freq);
                    double q   = rint(ang * 0.15915494309189535);
                    float red  = (float)(ang - q * 6.283185307179586);
                    float sn, cs;
                    sincosf(red, &sn, &cs);
                    float e2 = e * cs - od * sn;
                    od = e * sn + od * cs;
                    e = e2;
                }
                *(float2*)&o[nf * 8] = make_float2(e, od);
            }
        }
    }
}

// ============================================================================
// Flash attention v2: tf32 mma.sync for QK^T and PV.
// Q-tile 128 x kv-tile 64 x d 128. 8 warps; warp w owns q rows [16w,16w+16).
// smem strides: Qs/Ks 132 floats, Vt/Ps 68 floats  -> (4g+cl) conflict-free LDS.
// ============================================================================
#define QS_STRIDE 132
#define VT_STRIDE 68
#define PS_STRIDE 68
#define F_OFF_KS (128 * QS_STRIDE)                 // floats
#define F_OFF_VT (F_OFF_KS + 64 * QS_STRIDE)
#define F_OFF_PS (F_OFF_VT + 128 * VT_STRIDE)
#define FLASH2_SMEM ((F_OFF_PS + 128 * PS_STRIDE) * 4)   // 171008 B
#define L2E 1.4426950408889634f

__global__ __launch_bounds__(256, 1) void flash_mma()
{
    extern __shared__ float smf[];
    float* Qs = smf;
    float* Ks = smf + F_OFF_KS;
    float* Vt = smf + F_OFF_VT;
    float* Ps = smf + F_OFF_PS;

    const int tid  = threadIdx.x;
    const int w    = tid >> 5;
    const int lane = tid & 31;
    const int g    = lane >> 2;
    const int cl   = lane & 3;
    const int qt   = (gridDim.x - 1) - blockIdx.x;   // heavy tiles first
    const int bh   = blockIdx.y;
    const int q0   = qt * 128;
    const int wrow = w * 16;
    const float scale = 0.08838834764831845f;        // 1/sqrt(128)

    // ---- load Q tile (scaled + tf32-rounded) ----
    #pragma unroll
    for (int it = 0; it < 16; it++) {
        int idx = tid + it * 256;
        int r   = idx >> 5;
        int d0  = (idx & 31) << 2;
        float4 v = *(const float4*)&g_Q[(size_t)(bh * SEQ + q0 + r) * DK + d0];
        v.x = rtf32(v.x * scale); v.y = rtf32(v.y * scale);
        v.z = rtf32(v.z * scale); v.w = rtf32(v.w * scale);
        *(float4*)&Qs[r * QS_STRIDE + d0] = v;
    }

    float oacc[16][4];
    #pragma unroll
    for (int i = 0; i < 16; i++)
        #pragma unroll
        for (int k = 0; k < 4; k++) oacc[i][k] = 0.0f;
    float mrow[2] = {-INFINITY, -INFINITY};
    float lrow[2] = {0.0f, 0.0f};

    const int vr  = tid >> 2;        // 0..63 (V source row)
    const int vc4 = tid & 3;         // d-group

    const int ktiles = 2 * qt + 2;
    for (int kt = 0; kt < ktiles; kt++) {
        const int k0 = kt * 64;
        __syncthreads();             // prior tile's Ks/Vt consumers done

        // ---- load K tile [64 x 128] (rounded) ----
        #pragma unroll
        for (int it = 0; it < 8; it++) {
            int idx = tid + it * 256;
            int r   = idx >> 5;
            int d0  = (idx & 31) << 2;
            float4 v = *(const float4*)&g_K[(size_t)(bh * SEQ + k0 + r) * DK + d0];
            v.x = rtf32(v.x); v.y = rtf32(v.y); v.z = rtf32(v.z); v.w = rtf32(v.w);
            *(float4*)&Ks[r * QS_STRIDE + d0] = v;
        }
        // ---- load V tile transposed -> Vt[d][kv] (rounded) ----
        #pragma unroll
        for (int dblk = 0; dblk < 8; dblk++) {
            int d0 = dblk * 16 + vc4 * 4;
            float4 v = *(const float4*)&g_V[(size_t)(bh * SEQ + k0 + vr) * DK + d0];
            Vt[(d0 + 0) * VT_STRIDE + vr] = rtf32(v.x);
            Vt[(d0 + 1) * VT_STRIDE + vr] = rtf32(v.y);
            Vt[(d0 + 2) * VT_STRIDE + vr] = rtf32(v.z);
            Vt[(d0 + 3) * VT_STRIDE + vr] = rtf32(v.w);
        }
        __syncthreads();

        // ---- S = Q K^T : warp rows [wrow, wrow+16), cols [0,64) ----
        float sacc[8][4];
        #pragma unroll
        for (int nf = 0; nf < 8; nf++)
            #pragma unroll
            for (int k = 0; k < 4; k++) sacc[nf][k] = 0.0f;

        #pragma unroll
        for (int ks = 0; ks < 16; ks++) {
            uint32_t a0, a1, a2, a3;
            int ao = (wrow + g) * QS_STRIDE + ks * 8 + cl;
            a0 = __float_as_uint(Qs[ao]);
            a1 = __float_as_uint(Qs[ao + 8 * QS_STRIDE]);
            a2 = __float_as_uint(Qs[ao + 4]);
            a3 = __float_as_uint(Qs[ao + 8 * QS_STRIDE + 4]);
            #pragma unroll
            for (int nf = 0; nf < 8; nf++) {
                int bo = (nf * 8 + g) * QS_STRIDE + ks * 8 + cl;
                uint32_t b0 = __float_as_uint(Ks[bo]);
                uint32_t b1 = __float_as_uint(Ks[bo + 4]);
                mma_tf32(sacc[nf][0], sacc[nf][1], sacc[nf][2], sacc[nf][3],
                         a0, a1, a2, a3, b0, b1);
            }
        }

        // ---- causal mask (only tiles crossing the diagonal for this warp) ----
        if (k0 + 63 > q0 + wrow) {
            #pragma unroll
            for (int nf = 0; nf < 8; nf++)
                #pragma unroll
                for (int k = 0; k < 4; k++) {
                    int row = q0 + wrow + g + (k >> 1) * 8;
                    int col = k0 + nf * 8 + cl * 2 + (k & 1);
                    if (col > row) sacc[nf][k] = -INFINITY;
                }
        }

        // ---- online softmax (rows g, g+8; stats duplicated over 4 cl lanes) ----
        #pragma unroll
        for (int h = 0; h < 2; h++) {
            float mt = -INFINITY;
            #pragma unroll
            for (int nf = 0; nf < 8; nf++)
                mt = fmaxf(mt, fmaxf(sacc[nf][h * 2], sacc[nf][h * 2 + 1]));
            mt = fmaxf(mt, __shfl_xor_sync(0xffffffffu, mt, 1));
            mt = fmaxf(mt, __shfl_xor_sync(0xffffffffu, mt, 2));
            float mnew  = fmaxf(mrow[h], mt);
            float alpha = exp2f((mrow[h] - mnew) * L2E);
            float psum  = 0.0f;
            float* prow = &Ps[(wrow + g + h * 8) * PS_STRIDE + cl * 2];
            #pragma unroll
            for (int nf = 0; nf < 8; nf++) {
                float p0 = exp2f((sacc[nf][h * 2]     - mnew) * L2E);
                float p1 = exp2f((sacc[nf][h * 2 + 1] - mnew) * L2E);
                psum += p0 + p1;
                *(float2*)&prow[nf * 8] = make_float2(rtf32(p0), rtf32(p1));
            }
            psum += __shfl_xor_sync(0xffffffffu, psum, 1);
            psum += __shfl_xor_sync(0xffffffffu, psum, 2);
            lrow[h] = lrow[h] * alpha + psum;
            mrow[h] = mnew;
            #pragma unroll
            for (int nf2 = 0; nf2 < 16; nf2++) {
                oacc[nf2][h * 2]     *= alpha;
                oacc[nf2][h * 2 + 1] *= alpha;
            }
        }
        __syncwarp();   // Ps produced by own warp's lanes, consumed cross-lane

        // ---- O += P * V : rows [wrow,wrow+16), cols [0,128) ----
        #pragma unroll
        for (int ks = 0; ks < 8; ks++) {
            uint32_t a0, a1, a2, a3;
            int ao = (wrow + g) * PS_STRIDE + ks * 8 + cl;
            a0 = __float_as_uint(Ps[ao]);
            a1 = __float_as_uint(Ps[ao + 8 * PS_STRIDE]);
            a2 = __float_as_uint(Ps[ao + 4]);
            a3 = __float_as_uint(Ps[ao + 8 * PS_STRIDE + 4]);
            #pragma unroll
            for (int nf2 = 0; nf2 < 16; nf2++) {
                int bo = (nf2 * 8 + g) * VT_STRIDE + ks * 8 + cl;
                uint32_t b0 = __float_as_uint(Vt[bo]);
                uint32_t b1 = __float_as_uint(Vt[bo + 4]);
                mma_tf32(oacc[nf2][0], oacc[nf2][1], oacc[nf2][2], oacc[nf2][3],
                         a0, a1, a2, a3, b0, b1);
            }
        }
    }

    // ---- epilogue: scale by 1/l, tf32-round (feeds wo GEMM), store ----
    const int b  = bh >> 4;
    const int hh = bh & 15;
    #pragma unroll
    for (int h = 0; h < 2; h++) {
        float inv = 1.0f / lrow[h];
        int row = q0 + wrow + g + h * 8;
        float* o = &g_att[(size_t)(b * SEQ + row) * D_MODEL + hh * DK + cl * 2];
        #pragma unroll
        for (int nf2 = 0; nf2 < 16; nf2++)
            *(float2*)&o[nf2 * 8] =
                make_float2(rtf32(oacc[nf2][h * 2]     * inv),
                            rtf32(oacc[nf2][h * 2 + 1] * inv));
    }
}

// ============================================================================
extern "C" void kernel_launch(void* const* d_in, const int* in_sizes, int n_in,
                              void* d_out, int out_size)
{
    const float* x   = (const float*)d_in[0];
    const float* wq  = (const float*)d_in[1];
    const float* wk  = (const float*)d_in[2];
    const float* wv  = (const float*)d_in[3];
    const float* wo  = (const float*)d_in[4];
    const int*   pos = (const int*)  d_in[5];
    float* out = (float*)d_out;

    cudaFuncSetAttribute(gemm_mma, cudaFuncAttributeMaxDynamicSharedMemorySize,
                         GEMM_SMEM);
    cudaFuncSetAttribute(flash_mma, cudaFuncAttributeMaxDynamicSharedMemorySize,
                         FLASH2_SMEM);

    round_tf32<<<(MDIM*KDIM)/1024, 256>>>(x,  0);
    round_tf32<<<(KDIM*KDIM)/1024, 256>>>(wq, 1);
    round_tf32<<<(KDIM*KDIM)/1024, 256>>>(wk, 2);
    round_tf32<<<(KDIM*KDIM)/1024, 256>>>(wv, 3);
    round_tf32<<<(KDIM*KDIM)/1024, 256>>>(wo, 4);

    dim3 gg(D_MODEL / 128, MDIM / 128);   // 16 x 32
    gemm_mma<<<gg, 256, GEMM_SMEM>>>(nullptr, pos, 0);   // Q + RoPE
    gemm_mma<<<gg, 256, GEMM_SMEM>>>(nullptr, pos, 1);   // K + RoPE
    gemm_mma<<<gg, 256, GEMM_SMEM>>>(nullptr, pos, 2);   // V
    flash_mma<<<dim3(SEQ / 128, BATCH * NH), 256, FLASH2_SMEM>>>();
    gemm_mma<<<gg, 256, GEMM_SMEM>>>(out, pos, 3);       // output projection
}

// round 6
// speedup vs baseline: 4.4190x; 1.0855x over previous
#include <cuda_runtime.h>
#include <math.h>
#include <stdint.h>

#define D_MODEL 2048
#define NH      16
#define DK      128
#define SEQ     2048
#define BATCH   2
#define KDIM    2048
#define MDIM    (BATCH*SEQ)   // 4096

// -------- scratch (static device memory; no cudaMalloc allowed) ------------
__device__ float g_Q  [BATCH*NH*SEQ*DK];     // [b,h,s,d]  (tf32-rounded, post-RoPE)
__device__ float g_K  [BATCH*NH*SEQ*DK];     // [b,h,s,d]  (tf32-rounded, post-RoPE)
__device__ float g_Vt [BATCH*NH*DK*SEQ];     // [b,h,d,s]  (tf32-rounded, transposed)
__device__ float g_att[BATCH*SEQ*D_MODEL];   // [b,s,h*128+d] (tf32-rounded)
__device__ float g_xr [MDIM*KDIM];           // tf32-rounded x
__device__ float g_wqr[KDIM*KDIM];
__device__ float g_wkr[KDIM*KDIM];
__device__ float g_wvr[KDIM*KDIM];
__device__ float g_wor[KDIM*KDIM];
__device__ float g_rc [SEQ*64];              // RoPE cos LUT [s][d/2]
__device__ float g_rs [SEQ*64];              // RoPE sin LUT

// ============================================================================
// helpers
// ============================================================================
__device__ __forceinline__ float rtf32(float x) {
    uint32_t r;
    asm("cvt.rna.tf32.f32 %0, %1;" : "=r"(r) : "f"(x));
    return __uint_as_float(r);
}

__device__ __forceinline__ uint32_t smem_u32(const void* p) {
    uint32_t a;
    asm("{ .reg .u64 t; cvta.to.shared.u64 t, %1; cvt.u32.u64 %0, t; }"
        : "=r"(a) : "l"(p));
    return a;
}

#define CP16(dst, src) \
    asm volatile("cp.async.cg.shared.global [%0], [%1], 16;" \
                 :: "r"(dst), "l"(src) : "memory")
#define CP_COMMIT()  asm volatile("cp.async.commit_group;" ::: "memory")
#define CP_WAIT(n)   asm volatile("cp.async.wait_group %0;" :: "n"(n) : "memory")

__device__ __forceinline__ void mma_tf32(float& d0, float& d1, float& d2, float& d3,
                                         uint32_t a0, uint32_t a1, uint32_t a2, uint32_t a3,
                                         uint32_t b0, uint32_t b1) {
    asm volatile(
        "mma.sync.aligned.m16n8k8.row.col.f32.tf32.tf32.f32 "
        "{%0,%1,%2,%3}, {%4,%5,%6,%7}, {%8,%9}, {%0,%1,%2,%3};"
        : "+f"(d0), "+f"(d1), "+f"(d2), "+f"(d3)
        : "r"(a0), "r"(a1), "r"(a2), "r"(a3), "r"(b0), "r"(b1));
}

// ============================================================================
// prep: round fp32 -> tf32 (RNA).  mode: 0=x, 1..4 = wq,wk,wv,wo
// ============================================================================
__global__ void round_tf32(const float* __restrict__ src, int mode)
{
    float* dst = (mode == 0) ? g_xr :
                 (mode == 1) ? g_wqr :
                 (mode == 2) ? g_wkr :
                 (mode == 3) ? g_wvr : g_wor;
    size_t i = ((size_t)blockIdx.x * blockDim.x + threadIdx.x) * 4;
    float4 v = *(const float4*)&src[i];
    v.x = rtf32(v.x); v.y = rtf32(v.y); v.z = rtf32(v.z); v.w = rtf32(v.w);
    *(float4*)&dst[i] = v;
}

// ============================================================================
// prep: RoPE cos/sin LUT. One thread per (s, d/2). Same math as before, once.
// ============================================================================
__global__ void rope_lut(const int* __restrict__ pos)
{
    int idx = blockIdx.x * 256 + threadIdx.x;   // 0 .. SEQ*64-1
    int s = idx >> 6;
    int j = idx & 63;                            // d = 2j
    float freq = (float)exp(-(double)(2 * j) * (9.210340371976184 / 128.0));
    float p = (float)pos[s];
    double ang = (double)(p * freq);
    double q   = rint(ang * 0.15915494309189535);
    float red  = (float)(ang - q * 6.283185307179586);
    float sn, cs;
    sincosf(red, &sn, &cs);
    g_rc[idx] = cs;
    g_rs[idx] = sn;
}

// ============================================================================
// tf32 mma.sync NT GEMM core.
// MODE 0: fused QKV.  grid (48, 32): blockIdx.x -> wsel = x%3, head = x/3.
//         epilogue: Q/K -> RoPE(LUT) + rtf32 -> g_Q/g_K;
//                   V -> rtf32 + smem transpose -> g_Vt[b,h,d,s].
// MODE 1: wo.  grid (16, 32), A = g_att, raw fp32 -> Cout.
// ============================================================================
#define TSTRIDE 36
#define TILEF   (128 * TSTRIDE)
#define STAGEF  (2 * TILEF)
#define GEMM_SMEM (2 * STAGEF * 4)   // 73728 B (also covers 128x132 transpose)

template<int MODE>
__global__ __launch_bounds__(256, 2) void gemm_mma(float* __restrict__ Cout)
{
    extern __shared__ float smf[];
    const int tid = threadIdx.x;
    const int wid = tid >> 5;
    const int lane = tid & 31;
    const int g = lane >> 2;
    const int cl = lane & 3;
    const int wm = wid & 3;
    const int wn = wid >> 2;
    const int m0 = blockIdx.y * 128;

    int wsel, hh, n0;
    if (MODE == 0) { wsel = blockIdx.x % 3; hh = blockIdx.x / 3; n0 = hh * 128; }
    else           { wsel = 3; hh = 0; n0 = blockIdx.x * 128; }

    const float* __restrict__ Ap = (MODE == 0) ? g_xr : g_att;
    const float* __restrict__ Bp = (MODE == 1) ? g_wor :
                                   (wsel == 0) ? g_wqr :
                                   (wsel == 1) ? g_wkr : g_wvr;
    const float* __restrict__ arow = Ap + (size_t)m0 * KDIM;
    const float* __restrict__ brow = Bp + (size_t)n0 * KDIM;

    const uint32_t sb = smem_u32(smf);
    const int ldr  = tid >> 3;
    const int ldc4 = (tid & 7) << 2;

    auto load_tile = [&](int stage, int kt) {
        uint32_t base = sb + stage * STAGEF * 4;
        #pragma unroll
        for (int i = 0; i < 4; i++) {
            int r = ldr + i * 32;
            uint32_t doff = base + (r * TSTRIDE + ldc4) * 4;
            CP16(doff,            &arow[(size_t)r * KDIM + kt + ldc4]);
            CP16(doff + TILEF*4,  &brow[(size_t)r * KDIM + kt + ldc4]);
        }
    };

    float acc[2][8][4];
    #pragma unroll
    for (int i = 0; i < 2; i++)
        #pragma unroll
        for (int j = 0; j < 8; j++)
            #pragma unroll
            for (int k = 0; k < 4; k++) acc[i][j][k] = 0.0f;

    load_tile(0, 0);
    CP_COMMIT();

    const int aoff0 = (wm * 32 + g) * TSTRIDE + cl;
    const int boff0 = (wn * 64 + g) * TSTRIDE + cl;

    for (int c = 0; c < 64; c++) {
        if (c + 1 < 64) {
            load_tile((c + 1) & 1, (c + 1) * 32);
            CP_COMMIT();
            CP_WAIT(1);
        } else {
            CP_WAIT(0);
        }
        __syncthreads();

        const float* As = smf + (c & 1) * STAGEF;
        const float* Bs = As + TILEF;

        #pragma unroll
        for (int ks = 0; ks < 4; ks++) {
            uint32_t a[2][4], b[8][2];
            #pragma unroll
            for (int mf = 0; mf < 2; mf++) {
                int o = aoff0 + mf * 16 * TSTRIDE + ks * 8;
                a[mf][0] = __float_as_uint(As[o]);
                a[mf][1] = __float_as_uint(As[o + 8 * TSTRIDE]);
                a[mf][2] = __float_as_uint(As[o + 4]);
                a[mf][3] = __float_as_uint(As[o + 8 * TSTRIDE + 4]);
            }
            #pragma unroll
            for (int nf = 0; nf < 8; nf++) {
                int o = boff0 + nf * 8 * TSTRIDE + ks * 8;
                b[nf][0] = __float_as_uint(Bs[o]);
                b[nf][1] = __float_as_uint(Bs[o + 4]);
            }
            #pragma unroll
            for (int mf = 0; mf < 2; mf++)
                #pragma unroll
                for (int nf = 0; nf < 8; nf++)
                    mma_tf32(acc[mf][nf][0], acc[mf][nf][1],
                             acc[mf][nf][2], acc[mf][nf][3],
                             a[mf][0], a[mf][1], a[mf][2], a[mf][3],
                             b[nf][0], b[nf][1]);
        }
        __syncthreads();
    }

    // ---- epilogues ----
    if (MODE == 1) {
        #pragma unroll
        for (int mf = 0; mf < 2; mf++)
            #pragma unroll
            for (int half = 0; half < 2; half++) {
                int m = m0 + wm * 32 + mf * 16 + g + half * 8;
                float* o = &Cout[(size_t)m * D_MODEL + n0 + wn * 64 + cl * 2];
                #pragma unroll
                for (int nf = 0; nf < 8; nf++)
                    *(float2*)&o[nf * 8] =
                        make_float2(acc[mf][nf][half * 2], acc[mf][nf][half * 2 + 1]);
            }
        return;
    }

    if (wsel == 2) {
        // V: rtf32, transpose through smem, write g_Vt[b,h,d,s] coalesced.
        float* T = smf;                       // 128 x 132 (<= GEMM_SMEM floats)
        #pragma unroll
        for (int mf = 0; mf < 2; mf++)
            #pragma unroll
            for (int half = 0; half < 2; half++) {
                int sl = wm * 32 + mf * 16 + g + half * 8;
                #pragma unroll
                for (int nf = 0; nf < 8; nf++) {
                    int dl = wn * 64 + nf * 8 + cl * 2;
                    T[dl * 132 + sl]       = rtf32(acc[mf][nf][half * 2]);
                    T[(dl + 1) * 132 + sl] = rtf32(acc[mf][nf][half * 2 + 1]);
                }
            }
        __syncthreads();
        const int b = m0 >> 11;
        const int srow0 = m0 & 2047;
        #pragma unroll
        for (int i = 0; i < 16; i++) {
            int idx = tid + i * 256;
            int r   = idx >> 5;               // d row 0..127
            int c4  = (idx & 31) << 2;        // s col
            float4 v = *(float4*)&T[r * 132 + c4];
            *(float4*)&g_Vt[((size_t)((b * NH + hh) * DK + r)) * SEQ + srow0 + c4] = v;
        }
        return;
    }

    // Q or K: RoPE via LUT, rtf32, store [b,h,s,d]
    float* dptr = (wsel == 0) ? g_Q : g_K;
    #pragma unroll
    for (int mf = 0; mf < 2; mf++)
        #pragma unroll
        for (int half = 0; half < 2; half++) {
            int m = m0 + wm * 32 + mf * 16 + g + half * 8;
            int b = m >> 11;
            int s = m & 2047;
            const float* lc = &g_rc[s * 64 + wn * 32 + cl];
            const float* ls = &g_rs[s * 64 + wn * 32 + cl];
            float* o = &dptr[(size_t)((b * NH + hh) * SEQ + s) * DK + wn * 64 + cl * 2];
            #pragma unroll
            for (int nf = 0; nf < 8; nf++) {
                float cs = lc[nf * 4];
                float sn = ls[nf * 4];
                float e  = acc[mf][nf][half * 2];
                float od = acc[mf][nf][half * 2 + 1];
                *(float2*)&o[nf * 8] = make_float2(rtf32(e * cs - od * sn),
                                                   rtf32(e * sn + od * cs));
            }
        }
}

// ============================================================================
// Flash attention v3: tf32 mma, cp.async pipelined K (2-stage) + Vt (overlap
// fill with QK/softmax). V comes pre-transposed+rounded from the V epilogue.
// Q-tile 128 x kv-tile 64, 8 warps, warp w owns q rows [16w,16w+16).
// smem floats: Qs 128x132 | Ks 2x 64x132 | Vt 128x68 | Ps 128x68
// ============================================================================
#define FQ_OFF 0
#define FK_OFF 16896
#define FK_STG 8448
#define FV_OFF 33792
#define FP_OFF 42496
#define FLASH_SMEM (51200 * 4)               // 204800 B
#define L2E 1.4426950408889634f

__global__ __launch_bounds__(256, 1) void flash_mma()
{
    extern __shared__ float smf[];
    const uint32_t sb = smem_u32(smf);
    float* Qs = smf;
    float* Vt = smf + FV_OFF;
    float* Ps = smf + FP_OFF;

    const int tid  = threadIdx.x;
    const int w    = tid >> 5;
    const int lane = tid & 31;
    const int g    = lane >> 2;
    const int cl   = lane & 3;
    const int qt   = (gridDim.x - 1) - blockIdx.x;   // heavy tiles first
    const int bh   = blockIdx.y;
    const int q0   = qt * 128;
    const int wrow = w * 16;
    const float scale = 0.08838834764831845f;        // 1/sqrt(128)

    auto issue_K = [&](int kt) {
        int st = kt & 1, k0 = kt * 64;
        #pragma unroll
        for (int i = 0; i < 8; i++) {
            int idx = tid + i * 256;
            int r = idx >> 5, c4 = (idx & 31) << 2;
            CP16(sb + (FK_OFF + st * FK_STG + r * 132 + c4) * 4,
                 &g_K[(size_t)(bh * SEQ + k0 + r) * DK + c4]);
        }
    };
    auto issue_V = [&](int kt) {
        int k0 = kt * 64;
        #pragma unroll
        for (int i = 0; i < 8; i++) {
            int idx = tid + i * 256;
            int d = idx >> 4, s4 = (idx & 15) << 2;
            CP16(sb + (FV_OFF + d * 68 + s4) * 4,
                 &g_Vt[((size_t)bh * DK + d) * SEQ + k0 + s4]);
        }
    };

    issue_K(0); CP_COMMIT();

    // ---- Q tile: LDG, scale, round, STS ----
    #pragma unroll
    for (int it = 0; it < 16; it++) {
        int idx = tid + it * 256;
        int r   = idx >> 5;
        int d0  = (idx & 31) << 2;
        float4 v = *(const float4*)&g_Q[(size_t)(bh * SEQ + q0 + r) * DK + d0];
        v.x = rtf32(v.x * scale); v.y = rtf32(v.y * scale);
        v.z = rtf32(v.z * scale); v.w = rtf32(v.w * scale);
        *(float4*)&Qs[r * 132 + d0] = v;
    }

    float oacc[16][4];
    #pragma unroll
    for (int i = 0; i < 16; i++)
        #pragma unroll
        for (int k = 0; k < 4; k++) oacc[i][k] = 0.0f;
    float mrow[2] = {-INFINITY, -INFINITY};
    float lrow[2] = {0.0f, 0.0f};

    const int ktiles = 2 * qt + 2;
    for (int kt = 0; kt < ktiles; kt++) {
        const int k0 = kt * 64;
        const float* Ks = smf + FK_OFF + (kt & 1) * FK_STG;

        __syncthreads();             // prev tile fully consumed; Q published (kt=0)
        issue_V(kt); CP_COMMIT();
        if (kt + 1 < ktiles) { issue_K(kt + 1); CP_COMMIT(); CP_WAIT(2); }
        else                 { CP_WAIT(1); }
        __syncthreads();             // Ks(kt) visible to all warps

        // ---- S = Q K^T ----
        float sacc[8][4];
        #pragma unroll
        for (int nf = 0; nf < 8; nf++)
            #pragma unroll
            for (int k = 0; k < 4; k++) sacc[nf][k] = 0.0f;

        #pragma unroll
        for (int ks = 0; ks < 16; ks++) {
            uint32_t a0, a1, a2, a3;
            int ao = (wrow + g) * 132 + ks * 8 + cl;
            a0 = __float_as_uint(Qs[ao]);
            a1 = __float_as_uint(Qs[ao + 8 * 132]);
            a2 = __float_as_uint(Qs[ao + 4]);
            a3 = __float_as_uint(Qs[ao + 8 * 132 + 4]);
            #pragma unroll
            for (int nf = 0; nf < 8; nf++) {
                int bo = (nf * 8 + g) * 132 + ks * 8 + cl;
                uint32_t b0 = __float_as_uint(Ks[bo]);
                uint32_t b1 = __float_as_uint(Ks[bo + 4]);
                mma_tf32(sacc[nf][0], sacc[nf][1], sacc[nf][2], sacc[nf][3],
                         a0, a1, a2, a3, b0, b1);
            }
        }

        // ---- causal mask ----
        if (k0 + 63 > q0 + wrow) {
            #pragma unroll
            for (int nf = 0; nf < 8; nf++)
                #pragma unroll
                for (int k = 0; k < 4; k++) {
                    int row = q0 + wrow + g + (k >> 1) * 8;
                    int col = k0 + nf * 8 + cl * 2 + (k & 1);
                    if (col > row) sacc[nf][k] = -INFINITY;
                }
        }

        // ---- online softmax ----
        #pragma unroll
        for (int h = 0; h < 2; h++) {
            float mt = -INFINITY;
            #pragma unroll
            for (int nf = 0; nf < 8; nf++)
                mt = fmaxf(mt, fmaxf(sacc[nf][h * 2], sacc[nf][h * 2 + 1]));
            mt = fmaxf(mt, __shfl_xor_sync(0xffffffffu, mt, 1));
            mt = fmaxf(mt, __shfl_xor_sync(0xffffffffu, mt, 2));
            float mnew  = fmaxf(mrow[h], mt);
            float alpha = exp2f((mrow[h] - mnew) * L2E);
            float psum  = 0.0f;
            float* prow = &Ps[(wrow + g + h * 8) * 68 + cl * 2];
            #pragma unroll
            for (int nf = 0; nf < 8; nf++) {
                float p0 = exp2f((sacc[nf][h * 2]     - mnew) * L2E);
                float p1 = exp2f((sacc[nf][h * 2 + 1] - mnew) * L2E);
                psum += p0 + p1;
                *(float2*)&prow[nf * 8] = make_float2(rtf32(p0), rtf32(p1));
            }
            psum += __shfl_xor_sync(0xffffffffu, psum, 1);
            psum += __shfl_xor_sync(0xffffffffu, psum, 2);
            lrow[h] = lrow[h] * alpha + psum;
            mrow[h] = mnew;
            #pragma unroll
            for (int nf2 = 0; nf2 < 16; nf2++) {
                oacc[nf2][h * 2]     *= alpha;
                oacc[nf2][h * 2 + 1] *= alpha;
            }
        }
        __syncwarp();                // Ps cross-lane within warp

        if (kt + 1 < ktiles) { CP_WAIT(1); }  // Vt(kt) done; K(kt+1) may pend
        else                 { CP_WAIT(0); }
        __syncthreads();             // Vt visible to all warps

        // ---- O += P * V ----
        #pragma unroll
        for (int ks = 0; ks < 8; ks++) {
            uint32_t a0, a1, a2, a3;
            int ao = (wrow + g) * 68 + ks * 8 + cl;
            a0 = __float_as_uint(Ps[ao]);
            a1 = __float_as_uint(Ps[ao + 8 * 68]);
            a2 = __float_as_uint(Ps[ao + 4]);
            a3 = __float_as_uint(Ps[ao + 8 * 68 + 4]);
            #pragma unroll
            for (int nf2 = 0; nf2 < 16; nf2++) {
                int bo = (nf2 * 8 + g) * 68 + ks * 8 + cl;
                uint32_t b0 = __float_as_uint(Vt[bo]);
                uint32_t b1 = __float_as_uint(Vt[bo + 4]);
                mma_tf32(oacc[nf2][0], oacc[nf2][1], oacc[nf2][2], oacc[nf2][3],
                         a0, a1, a2, a3, b0, b1);
            }
        }
    }

    // ---- epilogue ----
    const int b  = bh >> 4;
    const int hh = bh & 15;
    #pragma unroll
    for (int h = 0; h < 2; h++) {
        float inv = 1.0f / lrow[h];
        int row = q0 + wrow + g + h * 8;
        float* o = &g_att[(size_t)(b * SEQ + row) * D_MODEL + hh * DK + cl * 2];
        #pragma unroll
        for (int nf2 = 0; nf2 < 16; nf2++)
            *(float2*)&o[nf2 * 8] =
                make_float2(rtf32(oacc[nf2][h * 2]     * inv),
                            rtf32(oacc[nf2][h * 2 + 1] * inv));
    }
}

// ============================================================================
extern "C" void kernel_launch(void* const* d_in, const int* in_sizes, int n_in,
                              void* d_out, int out_size)
{
    const float* x   = (const float*)d_in[0];
    const float* wq  = (const float*)d_in[1];
    const float* wk  = (const float*)d_in[2];
    const float* wv  = (const float*)d_in[3];
    const float* wo  = (const float*)d_in[4];
    const int*   pos = (const int*)  d_in[5];
    float* out = (float*)d_out;

    cudaFuncSetAttribute(gemm_mma<0>, cudaFuncAttributeMaxDynamicSharedMemorySize,
                         GEMM_SMEM);
    cudaFuncSetAttribute(gemm_mma<1>, cudaFuncAttributeMaxDynamicSharedMemorySize,
                         GEMM_SMEM);
    cudaFuncSetAttribute(flash_mma, cudaFuncAttributeMaxDynamicSharedMemorySize,
                         FLASH_SMEM);

    round_tf32<<<(MDIM*KDIM)/1024, 256>>>(x,  0);
    round_tf32<<<(KDIM*KDIM)/1024, 256>>>(wq, 1);
    round_tf32<<<(KDIM*KDIM)/1024, 256>>>(wk, 2);
    round_tf32<<<(KDIM*KDIM)/1024, 256>>>(wv, 3);
    round_tf32<<<(KDIM*KDIM)/1024, 256>>>(wo, 4);
    rope_lut<<<(SEQ*64)/256, 256>>>(pos);

    gemm_mma<0><<<dim3(48, MDIM/128), 256, GEMM_SMEM>>>(nullptr);     // QKV fused
    flash_mma<<<dim3(SEQ/128, BATCH*NH), 256, FLASH_SMEM>>>();
    gemm_mma<1><<<dim3(D_MODEL/128, MDIM/128), 256, GEMM_SMEM>>>(out); // wo
}

// round 7
// speedup vs baseline: 8.0965x; 1.8322x over previous
#include <cuda_runtime.h>
#include <cuda_fp16.h>
#include <math.h>
#include <stdint.h>

#define D_MODEL 2048
#define NH      16
#define DK      128
#define SEQ     2048
#define BATCH   2
#define KDIM    2048
#define MDIM    (BATCH*SEQ)   // 4096

// -------- scratch (static device memory; no cudaMalloc allowed) ------------
__device__ __half g_Q  [BATCH*NH*SEQ*DK];     // [b,h,s,d] post-RoPE, pre-scaled
__device__ __half g_K  [BATCH*NH*SEQ*DK];     // [b,h,s,d] post-RoPE
__device__ __half g_Vt [BATCH*NH*DK*SEQ];     // [b,h,d,s] transposed
__device__ __half g_att[BATCH*SEQ*D_MODEL];   // [b,s,h*128+d]
__device__ __half g_xh [MDIM*KDIM];           // fp16 x
__device__ __half g_wqh[KDIM*KDIM];
__device__ __half g_wkh[KDIM*KDIM];
__device__ __half g_wvh[KDIM*KDIM];
__device__ __half g_woh[KDIM*KDIM];
__device__ float  g_rc [SEQ*64];              // RoPE cos LUT [s][d/2]
__device__ float  g_rs [SEQ*64];              // RoPE sin LUT

// ============================================================================
// helpers
// ============================================================================
__device__ __forceinline__ uint32_t smem_u32(const void* p) {
    uint32_t a;
    asm("{ .reg .u64 t; cvta.to.shared.u64 t, %1; cvt.u32.u64 %0, t; }"
        : "=r"(a) : "l"(p));
    return a;
}

#define CP16(dst, src) \
    asm volatile("cp.async.cg.shared.global [%0], [%1], 16;" \
                 :: "r"(dst), "l"(src) : "memory")
#define CP_COMMIT()  asm volatile("cp.async.commit_group;" ::: "memory")
#define CP_WAIT(n)   asm volatile("cp.async.wait_group %0;" :: "n"(n) : "memory")

__device__ __forceinline__ void mma_f16(float& d0, float& d1, float& d2, float& d3,
                                        uint32_t a0, uint32_t a1, uint32_t a2, uint32_t a3,
                                        uint32_t b0, uint32_t b1) {
    asm volatile(
        "mma.sync.aligned.m16n8k16.row.col.f32.f16.f16.f32 "
        "{%0,%1,%2,%3}, {%4,%5,%6,%7}, {%8,%9}, {%0,%1,%2,%3};"
        : "+f"(d0), "+f"(d1), "+f"(d2), "+f"(d3)
        : "r"(a0), "r"(a1), "r"(a2), "r"(a3), "r"(b0), "r"(b1));
}

// ============================================================================
// prep: fp32 -> fp16 (RN).  mode: 0=x, 1..4 = wq,wk,wv,wo.  8 elems/thread.
// ============================================================================
__global__ void to_half(const float* __restrict__ src, int mode)
{
    __half* dst = (mode == 0) ? g_xh :
                  (mode == 1) ? g_wqh :
                  (mode == 2) ? g_wkh :
                  (mode == 3) ? g_wvh : g_woh;
    size_t i = ((size_t)blockIdx.x * blockDim.x + threadIdx.x) * 8;
    float4 v0 = *(const float4*)&src[i];
    float4 v1 = *(const float4*)&src[i + 4];
    __half2 h[4];
    h[0] = __floats2half2_rn(v0.x, v0.y);
    h[1] = __floats2half2_rn(v0.z, v0.w);
    h[2] = __floats2half2_rn(v1.x, v1.y);
    h[3] = __floats2half2_rn(v1.z, v1.w);
    *(uint4*)&dst[i] = *(uint4*)h;
}

// ============================================================================
// prep: RoPE cos/sin LUT
// ============================================================================
__global__ void rope_lut(const int* __restrict__ pos)
{
    int idx = blockIdx.x * 256 + threadIdx.x;   // 0 .. SEQ*64-1
    int s = idx >> 6;
    int j = idx & 63;                            // d = 2j
    float freq = (float)exp(-(double)(2 * j) * (9.210340371976184 / 128.0));
    float p = (float)pos[s];
    double ang = (double)(p * freq);
    double q   = rint(ang * 0.15915494309189535);
    float red  = (float)(ang - q * 6.283185307179586);
    float sn, cs;
    sincosf(red, &sn, &cs);
    g_rc[idx] = cs;
    g_rs[idx] = sn;
}

// ============================================================================
// fp16 mma.sync NT GEMM: C = A * B^T (A[M,K], B[N,K] row-major, half).
// Tile 128x128, BK=64 halves, 256 thr, warp tile 32x64, fp32 accum.
// MODE 0: fused QKV (grid 48 x 32; wsel = x%3, head = x/3).
//   Q: scale+RoPE -> g_Q;  K: RoPE -> g_K;  V: transpose -> g_Vt.
// MODE 1: wo (grid 16 x 32), A = g_att, fp32 out -> Cout.
// ============================================================================
#define TSTR   72                      // halves per smem row (36 words = 4 mod 32)
#define TILEH  (128 * TSTR)            // 9216 halves
#define STAGEH (2 * TILEH)
#define GEMM_SMEM (2 * STAGEH * 2)     // 73728 B
#define QSCALE 0.08838834764831845f

template<int MODE>
__global__ __launch_bounds__(256, 2) void gemm_mma(float* __restrict__ Cout)
{
    extern __shared__ char smc[];
    __half* smh = (__half*)smc;
    const int tid = threadIdx.x;
    const int wid = tid >> 5;
    const int lane = tid & 31;
    const int g = lane >> 2;
    const int cl = lane & 3;
    const int wm = wid & 3;
    const int wn = wid >> 2;
    const int m0 = blockIdx.y * 128;

    int wsel, hh, n0;
    if (MODE == 0) { wsel = blockIdx.x % 3; hh = blockIdx.x / 3; n0 = hh * 128; }
    else           { wsel = 3; hh = 0; n0 = blockIdx.x * 128; }

    const __half* __restrict__ Ap = (MODE == 0) ? g_xh : g_att;
    const __half* __restrict__ Bp = (MODE == 1) ? g_woh :
                                    (wsel == 0) ? g_wqh :
                                    (wsel == 1) ? g_wkh : g_wvh;
    const __half* __restrict__ arow = Ap + (size_t)m0 * KDIM;
    const __half* __restrict__ brow = Bp + (size_t)n0 * KDIM;

    const uint32_t sb = smem_u32(smc);
    const int ldr = tid >> 3;           // 0..31
    const int ldc = (tid & 7) * 8;      // half offset 0..56

    auto load_tile = [&](int stage, int kt) {
        uint32_t base = sb + stage * STAGEH * 2;
        #pragma unroll
        for (int i = 0; i < 4; i++) {
            int r = ldr + i * 32;
            uint32_t doff = base + (r * TSTR + ldc) * 2;
            CP16(doff,             &arow[(size_t)r * KDIM + kt + ldc]);
            CP16(doff + TILEH * 2, &brow[(size_t)r * KDIM + kt + ldc]);
        }
    };

    float acc[2][8][4];
    #pragma unroll
    for (int i = 0; i < 2; i++)
        #pragma unroll
        for (int j = 0; j < 8; j++)
            #pragma unroll
            for (int k = 0; k < 4; k++) acc[i][j][k] = 0.0f;

    load_tile(0, 0);
    CP_COMMIT();

    const int aoff0 = (wm * 32 + g) * 36 + cl;   // word units
    const int boff0 = (wn * 64 + g) * 36 + cl;

    for (int c = 0; c < 32; c++) {
        if (c + 1 < 32) {
            load_tile((c + 1) & 1, (c + 1) * 64);
            CP_COMMIT();
            CP_WAIT(1);
        } else {
            CP_WAIT(0);
        }
        __syncthreads();

        const uint32_t* As32 = (const uint32_t*)(smh + (c & 1) * STAGEH);
        const uint32_t* Bs32 = As32 + TILEH / 2;

        #pragma unroll
        for (int ks = 0; ks < 4; ks++) {
            uint32_t a[2][4], b[8][2];
            #pragma unroll
            for (int mf = 0; mf < 2; mf++) {
                int o = aoff0 + mf * 16 * 36 + ks * 8;
                a[mf][0] = As32[o];
                a[mf][1] = As32[o + 8 * 36];
                a[mf][2] = As32[o + 4];
                a[mf][3] = As32[o + 8 * 36 + 4];
            }
            #pragma unroll
            for (int nf = 0; nf < 8; nf++) {
                int o = boff0 + nf * 8 * 36 + ks * 8;
                b[nf][0] = Bs32[o];
                b[nf][1] = Bs32[o + 4];
            }
            #pragma unroll
            for (int mf = 0; mf < 2; mf++)
                #pragma unroll
                for (int nf = 0; nf < 8; nf++)
                    mma_f16(acc[mf][nf][0], acc[mf][nf][1],
                            acc[mf][nf][2], acc[mf][nf][3],
                            a[mf][0], a[mf][1], a[mf][2], a[mf][3],
                            b[nf][0], b[nf][1]);
        }
        __syncthreads();
    }

    // ---- epilogues ----
    if (MODE == 1) {
        #pragma unroll
        for (int mf = 0; mf < 2; mf++)
            #pragma unroll
            for (int half = 0; half < 2; half++) {
                int m = m0 + wm * 32 + mf * 16 + g + half * 8;
                float* o = &Cout[(size_t)m * D_MODEL + n0 + wn * 64 + cl * 2];
                #pragma unroll
                for (int nf = 0; nf < 8; nf++)
                    *(float2*)&o[nf * 8] =
                        make_float2(acc[mf][nf][half * 2], acc[mf][nf][half * 2 + 1]);
            }
        return;
    }

    if (wsel == 2) {
        // V: fp16, transpose through smem, write g_Vt[b,h,d,s] coalesced.
        __half* T = smh;                       // 128 x 136 halves (34816 B)
        #pragma unroll
        for (int mf = 0; mf < 2; mf++)
            #pragma unroll
            for (int half = 0; half < 2; half++) {
                int sl = wm * 32 + mf * 16 + g + half * 8;
                #pragma unroll
                for (int nf = 0; nf < 8; nf++) {
                    int dl = wn * 64 + nf * 8 + cl * 2;
                    T[dl * 136 + sl]       = __float2half_rn(acc[mf][nf][half * 2]);
                    T[(dl + 1) * 136 + sl] = __float2half_rn(acc[mf][nf][half * 2 + 1]);
                }
            }
        __syncthreads();
        const int b = m0 >> 11;
        const int srow0 = m0 & 2047;
        #pragma unroll
        for (int i = 0; i < 8; i++) {
            int idx = tid + i * 256;
            int r   = idx >> 4;               // d row 0..127
            int c8  = (idx & 15) * 8;         // s col
            uint4 v = *(uint4*)&T[r * 136 + c8];
            *(uint4*)&g_Vt[((size_t)((b * NH + hh) * DK + r)) * SEQ + srow0 + c8] = v;
        }
        return;
    }

    // Q or K: (Q: fold 1/sqrt(dk)), RoPE via LUT, store half [b,h,s,d]
    __half* dptr = (wsel == 0) ? g_Q : g_K;
    const float qs = (wsel == 0) ? QSCALE : 1.0f;
    #pragma unroll
    for (int mf = 0; mf < 2; mf++)
        #pragma unroll
        for (int half = 0; half < 2; half++) {
            int m = m0 + wm * 32 + mf * 16 + g + half * 8;
            int b = m >> 11;
            int s = m & 2047;
            const float* lc = &g_rc[s * 64 + wn * 32 + cl];
            const float* ls = &g_rs[s * 64 + wn * 32 + cl];
            __half2* o = (__half2*)&dptr[(size_t)((b * NH + hh) * SEQ + s) * DK
                                         + wn * 64 + cl * 2];
            #pragma unroll
            for (int nf = 0; nf < 8; nf++) {
                float cs = lc[nf * 4];
                float sn = ls[nf * 4];
                float e  = acc[mf][nf][half * 2] * qs;
                float od = acc[mf][nf][half * 2 + 1] * qs;
                o[nf * 4] = __floats2half2_rn(e * cs - od * sn, e * sn + od * cs);
            }
        }
}

// ============================================================================
// Flash attention v4: fp16 mma, fully cp.async (Q, K 2-stage, Vt overlapped).
// Q-tile 128 x kv-tile 64, 8 warps, warp w owns q rows [16w,16w+16).
// smem halves: Qs 128x136 | Ks 2x 64x136 | Vt 128x72 | Ps 128x72
// ============================================================================
#define FQ  0
#define FKo (128 * 136)
#define FKS (64 * 136)
#define FV  (FKo + 2 * FKS)
#define FP  (FV + 128 * 72)
#define FLASH_SMEM ((FP + 128 * 72) * 2)     // 106496 B
#define L2E 1.4426950408889634f

__global__ __launch_bounds__(256, 1) void flash_mma()
{
    extern __shared__ char smc[];
    __half* smh = (__half*)smc;
    const uint32_t sb = smem_u32(smc);

    const int tid  = threadIdx.x;
    const int w    = tid >> 5;
    const int lane = tid & 31;
    const int g    = lane >> 2;
    const int cl   = lane & 3;
    const int qt   = (gridDim.x - 1) - blockIdx.x;   // heavy tiles first
    const int bh   = blockIdx.y;
    const int q0   = qt * 128;
    const int wrow = w * 16;

    auto issue_Q = [&]() {
        #pragma unroll
        for (int i = 0; i < 8; i++) {
            int idx = tid + i * 256;
            int r = idx >> 4, c8 = (idx & 15) * 8;
            CP16(sb + (r * 136 + c8) * 2,
                 &g_Q[(size_t)(bh * SEQ + q0 + r) * DK + c8]);
        }
    };
    auto issue_K = [&](int kt) {
        int st = kt & 1, k0 = kt * 64;
        #pragma unroll
        for (int i = 0; i < 4; i++) {
            int idx = tid + i * 256;
            int r = idx >> 4, c8 = (idx & 15) * 8;
            CP16(sb + (FKo + st * FKS + r * 136 + c8) * 2,
                 &g_K[(size_t)(bh * SEQ + k0 + r) * DK + c8]);
        }
    };
    auto issue_V = [&](int kt) {
        int k0 = kt * 64;
        #pragma unroll
        for (int i = 0; i < 4; i++) {
            int idx = tid + i * 256;
            int d = idx >> 3, c8 = (idx & 7) * 8;
            CP16(sb + (FV + d * 72 + c8) * 2,
                 &g_Vt[((size_t)bh * DK + d) * SEQ + k0 + c8]);
        }
    };

    issue_K(0);
    issue_Q();
    CP_COMMIT();

    float oacc[16][4];
    #pragma unroll
    for (int i = 0; i < 16; i++)
        #pragma unroll
        for (int k = 0; k < 4; k++) oacc[i][k] = 0.0f;
    float mrow[2] = {-INFINITY, -INFINITY};
    float lrow[2] = {0.0f, 0.0f};

    const int ktiles = 2 * qt + 2;
    for (int kt = 0; kt < ktiles; kt++) {
        const int k0 = kt * 64;

        __syncthreads();             // prev tile fully consumed
        issue_V(kt); CP_COMMIT();
        if (kt + 1 < ktiles) { issue_K(kt + 1); CP_COMMIT(); CP_WAIT(2); }
        else                 { CP_WAIT(1); }
        __syncthreads();             // Q + Ks(kt) visible to all warps

        const uint32_t* Q32 = (const uint32_t*)smh;
        const uint32_t* K32 = (const uint32_t*)(smh + FKo + (kt & 1) * FKS);

        // ---- S = Q K^T ----
        float sacc[8][4];
        #pragma unroll
        for (int nf = 0; nf < 8; nf++)
            #pragma unroll
            for (int k = 0; k < 4; k++) sacc[nf][k] = 0.0f;

        #pragma unroll
        for (int ks = 0; ks < 8; ks++) {
            int ao = (wrow + g) * 68 + ks * 8 + cl;
            uint32_t a0 = Q32[ao];
            uint32_t a1 = Q32[ao + 8 * 68];
            uint32_t a2 = Q32[ao + 4];
            uint32_t a3 = Q32[ao + 8 * 68 + 4];
            #pragma unroll
            for (int nf = 0; nf < 8; nf++) {
                int bo = (nf * 8 + g) * 68 + ks * 8 + cl;
                uint32_t b0 = K32[bo];
                uint32_t b1 = K32[bo + 4];
                mma_f16(sacc[nf][0], sacc[nf][1], sacc[nf][2], sacc[nf][3],
                        a0, a1, a2, a3, b0, b1);
            }
        }

        // ---- causal mask ----
        if (k0 + 63 > q0 + wrow) {
            #pragma unroll
            for (int nf = 0; nf < 8; nf++)
                #pragma unroll
                for (int k = 0; k < 4; k++) {
                    int row = q0 + wrow + g + (k >> 1) * 8;
                    int col = k0 + nf * 8 + cl * 2 + (k & 1);
                    if (col > row) sacc[nf][k] = -INFINITY;
                }
        }

        // ---- online softmax (rows g, g+8) ----
        #pragma unroll
        for (int h = 0; h < 2; h++) {
            float mt = -INFINITY;
            #pragma unroll
            for (int nf = 0; nf < 8; nf++)
                mt = fmaxf(mt, fmaxf(sacc[nf][h * 2], sacc[nf][h * 2 + 1]));
            mt = fmaxf(mt, __shfl_xor_sync(0xffffffffu, mt, 1));
            mt = fmaxf(mt, __shfl_xor_sync(0xffffffffu, mt, 2));
            float mnew  = fmaxf(mrow[h], mt);
            float alpha = exp2f((mrow[h] - mnew) * L2E);
            float psum  = 0.0f;
            __half2* prow = (__half2*)(smh + FP + (wrow + g + h * 8) * 72) + cl;
            #pragma unroll
            for (int nf = 0; nf < 8; nf++) {
                float p0 = exp2f((sacc[nf][h * 2]     - mnew) * L2E);
                float p1 = exp2f((sacc[nf][h * 2 + 1] - mnew) * L2E);
                psum += p0 + p1;
                prow[nf * 4] = __floats2half2_rn(p0, p1);
            }
            psum += __shfl_xor_sync(0xffffffffu, psum, 1);
            psum += __shfl_xor_sync(0xffffffffu, psum, 2);
            lrow[h] = lrow[h] * alpha + psum;
            mrow[h] = mnew;
            #pragma unroll
            for (int nf2 = 0; nf2 < 16; nf2++) {
                oacc[nf2][h * 2]     *= alpha;
                oacc[nf2][h * 2 + 1] *= alpha;
            }
        }
        __syncwarp();                // Ps rows are warp-private; cross-lane only

        if (kt + 1 < ktiles) { CP_WAIT(1); }  // Vt(kt) done; K(kt+1) may pend
        else                 { CP_WAIT(0); }
        __syncthreads();             // Vt visible to all warps

        // ---- O += P * V ----
        const uint32_t* P32 = (const uint32_t*)(smh + FP);
        const uint32_t* V32 = (const uint32_t*)(smh + FV);
        #pragma unroll
        for (int ks = 0; ks < 4; ks++) {
            int ao = (wrow + g) * 36 + ks * 8 + cl;
            uint32_t a0 = P32[ao];
            uint32_t a1 = P32[ao + 8 * 36];
            uint32_t a2 = P32[ao + 4];
            uint32_t a3 = P32[ao + 8 * 36 + 4];
            #pragma unroll
            for (int nf2 = 0; nf2 < 16; nf2++) {
                int bo = (nf2 * 8 + g) * 36 + ks * 8 + cl;
                uint32_t b0 = V32[bo];
                uint32_t b1 = V32[bo + 4];
                mma_f16(oacc[nf2][0], oacc[nf2][1], oacc[nf2][2], oacc[nf2][3],
                        a0, a1, a2, a3, b0, b1);
            }
        }
    }

    // ---- epilogue: scale by 1/l, store half (feeds wo GEMM) ----
    const int b  = bh >> 4;
    const int hh = bh & 15;
    #pragma unroll
    for (int h = 0; h < 2; h++) {
        float inv = 1.0f / lrow[h];
        int row = q0 + wrow + g + h * 8;
        __half2* o = (__half2*)&g_att[(size_t)(b * SEQ + row) * D_MODEL
                                      + hh * DK + cl * 2];
        #pragma unroll
        for (int nf2 = 0; nf2 < 16; nf2++)
            o[nf2 * 4] = __floats2half2_rn(oacc[nf2][h * 2]     * inv,
                                           oacc[nf2][h * 2 + 1] * inv);
    }
}

// ============================================================================
extern "C" void kernel_launch(void* const* d_in, const int* in_sizes, int n_in,
                              void* d_out, int out_size)
{
    const float* x   = (const float*)d_in[0];
    const float* wq  = (const float*)d_in[1];
    const float* wk  = (const float*)d_in[2];
    const float* wv  = (const float*)d_in[3];
    const float* wo  = (const float*)d_in[4];
    const int*   pos = (const int*)  d_in[5];
    float* out = (float*)d_out;

    cudaFuncSetAttribute(gemm_mma<0>, cudaFuncAttributeMaxDynamicSharedMemorySize,
                         GEMM_SMEM);
    cudaFuncSetAttribute(gemm_mma<1>, cudaFuncAttributeMaxDynamicSharedMemorySize,
                         GEMM_SMEM);
    cudaFuncSetAttribute(flash_mma, cudaFuncAttributeMaxDynamicSharedMemorySize,
                         FLASH_SMEM);

    to_half<<<(MDIM*KDIM)/2048, 256>>>(x,  0);
    to_half<<<(KDIM*KDIM)/2048, 256>>>(wq, 1);
    to_half<<<(KDIM*KDIM)/2048, 256>>>(wk, 2);
    to_half<<<(KDIM*KDIM)/2048, 256>>>(wv, 3);
    to_half<<<(KDIM*KDIM)/2048, 256>>>(wo, 4);
    rope_lut<<<(SEQ*64)/256, 256>>>(pos);

    gemm_mma<0><<<dim3(48, MDIM/128), 256, GEMM_SMEM>>>(nullptr);      // QKV
    flash_mma<<<dim3(SEQ/128, BATCH*NH), 256, FLASH_SMEM>>>();
    gemm_mma<1><<<dim3(D_MODEL/128, MDIM/128), 256, GEMM_SMEM>>>(out); // wo
}